// round 1
// baseline (speedup 1.0000x reference)
#include <cuda_runtime.h>
#include <cuda_bf16.h>
#include <math.h>

// ---------------------------------------------------------------------------
// Problem constants (fixed by the reference)
// ---------------------------------------------------------------------------
#define G_   64
#define N_   256
#define GN_  (G_ * N_)        // 16384 nodes
#define H_   8
#define D_   32               // head dim
#define IN_  256
#define OUT_ 256
#define FF_  1024
#define E_   (GN_ * 16)       // 262144 edges
#define EPS_ 1e-5f

// ---------------------------------------------------------------------------
// Device scratch (no allocations allowed — static __device__ arrays)
// ---------------------------------------------------------------------------
__device__ float g_xn  [GN_ * IN_];    // layernorm1(x)
__device__ float g_q   [GN_ * OUT_];
__device__ float g_k   [GN_ * OUT_];
__device__ float g_v   [GN_ * OUT_];
__device__ float g_ew  [E_ * H_];      // edge bias per head
__device__ float g_xout[GN_ * OUT_];   // x + attn_out
__device__ float g_h   [GN_ * OUT_];   // layernorm2(x_out)
__device__ float g_ff1 [GN_ * FF_];    // relu(h @ Wf1 + bf1)

__device__ int g_counts [GN_];
__device__ int g_rowptr [GN_ + 1];
__device__ int g_cursor [GN_];
__device__ int g_csr_dst[E_];          // local dst (0..255)
__device__ int g_csr_eid[E_];          // original edge id
__device__ int g_is64;                 // edge_index dtype flag

// ---------------------------------------------------------------------------
// Helpers
// ---------------------------------------------------------------------------
__device__ __forceinline__ long long load_idx(const void* p, int i) {
    if (g_is64) return ((const long long*)p)[i];
    return (long long)(((const int*)p)[i]);
}

__device__ __forceinline__ float warp_sum(float v) {
    #pragma unroll
    for (int o = 16; o > 0; o >>= 1) v += __shfl_xor_sync(0xffffffffu, v, o);
    return v;
}
__device__ __forceinline__ float warp_max(float v) {
    #pragma unroll
    for (int o = 16; o > 0; o >>= 1) v = fmaxf(v, __shfl_xor_sync(0xffffffffu, v, o));
    return v;
}

// ---------------------------------------------------------------------------
// 0) detect edge_index dtype (int32 vs int64).  If the buffer holds int32
//    values, reading pairs as int64 yields values >= 2^32 (high word is a
//    nonzero node index for essentially every pair), so "all 512 in range"
//    identifies genuine int64 data.
// ---------------------------------------------------------------------------
__global__ void detect_kernel(const void* __restrict__ ei) {
    const long long* p = (const long long*)ei;
    int ok = 1;
    for (int i = 0; i < 512; ++i) {
        long long v = p[i];
        if (v < 0 || v >= GN_) { ok = 0; break; }
    }
    g_is64 = ok;
}

// ---------------------------------------------------------------------------
// CSR build: zero -> histogram -> scan -> scatter
// ---------------------------------------------------------------------------
__global__ void zero_counts_kernel() {
    int i = blockIdx.x * 256 + threadIdx.x;
    g_counts[i] = 0;
}

__global__ void hist_kernel(const void* __restrict__ ei) {
    int e = blockIdx.x * 256 + threadIdx.x;
    int src = (int)load_idx(ei, e);
    atomicAdd(&g_counts[src], 1);
}

__global__ void scan_kernel() {   // 1 block, 1024 threads, 16 counts each
    __shared__ int wsum[32];
    int t = threadIdx.x;
    int base = t * 16;
    int local[16];
    int s = 0;
    #pragma unroll
    for (int i = 0; i < 16; ++i) { local[i] = g_counts[base + i]; s += local[i]; }
    int lane = t & 31, w = t >> 5;
    int inc = s;
    #pragma unroll
    for (int o = 1; o < 32; o <<= 1) {
        int n = __shfl_up_sync(0xffffffffu, inc, o);
        if (lane >= o) inc += n;
    }
    if (lane == 31) wsum[w] = inc;
    __syncthreads();
    if (w == 0) {
        int v = wsum[lane];
        #pragma unroll
        for (int o = 1; o < 32; o <<= 1) {
            int n = __shfl_up_sync(0xffffffffu, v, o);
            if (lane >= o) v += n;
        }
        wsum[lane] = v;
    }
    __syncthreads();
    int run = inc - s + (w > 0 ? wsum[w - 1] : 0);
    #pragma unroll
    for (int i = 0; i < 16; ++i) {
        g_rowptr[base + i] = run;
        g_cursor[base + i] = run;
        run += local[i];
    }
    if (t == 1023) g_rowptr[GN_] = run;
}

__global__ void scatter_kernel(const void* __restrict__ ei) {
    int e = blockIdx.x * 256 + threadIdx.x;
    int src = (int)load_idx(ei, e);
    int dst = (int)load_idx(ei, E_ + e);
    int pos = atomicAdd(&g_cursor[src], 1);
    g_csr_dst[pos] = dst & (N_ - 1);
    g_csr_eid[pos] = e;
}

// ---------------------------------------------------------------------------
// Edge bias: ew[e,h] = edge_attr[e,:] @ We + be       (We is [2, 8])
// ---------------------------------------------------------------------------
__global__ void ew_kernel(const float* __restrict__ ea,
                          const float* __restrict__ We,
                          const float* __restrict__ be) {
    int e = blockIdx.x * 256 + threadIdx.x;
    float a0 = ea[2 * e], a1 = ea[2 * e + 1];
    #pragma unroll
    for (int h = 0; h < H_; ++h)
        g_ew[e * H_ + h] = a0 * We[h] + a1 * We[H_ + h] + be[h];
}

// ---------------------------------------------------------------------------
// LayerNorm: one warp per row of 256
// ---------------------------------------------------------------------------
__global__ __launch_bounds__(256) void ln_kernel(const float* __restrict__ x,
                                                 const float* __restrict__ w,
                                                 const float* __restrict__ b,
                                                 float* __restrict__ out) {
    int row  = blockIdx.x * 8 + (threadIdx.x >> 5);
    int lane = threadIdx.x & 31;
    const float* xr = x + (size_t)row * 256;
    float v[8];
    float s = 0.f;
    #pragma unroll
    for (int i = 0; i < 8; ++i) { v[i] = xr[lane + 32 * i]; s += v[i]; }
    s = warp_sum(s);
    float mean = s * (1.f / 256.f);
    float sq = 0.f;
    #pragma unroll
    for (int i = 0; i < 8; ++i) { float d = v[i] - mean; sq += d * d; }
    sq = warp_sum(sq);
    float rstd = rsqrtf(sq * (1.f / 256.f) + EPS_);
    float* orow = out + (size_t)row * 256;
    #pragma unroll
    for (int i = 0; i < 8; ++i) {
        int c = lane + 32 * i;
        orow[c] = (v[i] - mean) * rstd * w[c] + b[c];
    }
}

// ---------------------------------------------------------------------------
// Tiled fp32 GEMM:  C[M,Nn] = epilogue(A[M,K] @ B[K,Nn] + bias (+res))
// 128x128 tile, BK=16, 256 threads, 8x8 micro-tile. M%128==0, Nn%128==0, K%16==0.
// ---------------------------------------------------------------------------
template <bool RELU, bool HASRES>
__global__ __launch_bounds__(256) void gemm_kernel(
        const float* __restrict__ A, const float* __restrict__ B,
        const float* __restrict__ bias, const float* __restrict__ res,
        float* __restrict__ C, int M, int Nn, int K) {
    __shared__ float As[16][128];
    __shared__ float Bs[16][128];
    int tid = threadIdx.x;
    int tx = tid & 15, ty = tid >> 4;
    int m0 = blockIdx.y * 128, n0 = blockIdx.x * 128;
    float acc[8][8] = {};
    for (int k0 = 0; k0 < K; k0 += 16) {
        #pragma unroll
        for (int l = 0; l < 2; ++l) {       // A: 128x16 = 512 float4
            int idx = tid + 256 * l;
            int row = idx >> 2;
            int c4  = (idx & 3) << 2;
            float4 f = *(const float4*)(A + (size_t)(m0 + row) * K + k0 + c4);
            As[c4 + 0][row] = f.x; As[c4 + 1][row] = f.y;
            As[c4 + 2][row] = f.z; As[c4 + 3][row] = f.w;
        }
        #pragma unroll
        for (int l = 0; l < 2; ++l) {       // B: 16x128 = 512 float4
            int idx = tid + 256 * l;
            int row = idx >> 5;
            int c4  = (idx & 31) << 2;
            *(float4*)(&Bs[row][c4]) =
                *(const float4*)(B + (size_t)(k0 + row) * Nn + n0 + c4);
        }
        __syncthreads();
        #pragma unroll
        for (int kk = 0; kk < 16; ++kk) {
            float a[8], bb[8];
            #pragma unroll
            for (int i = 0; i < 8; ++i) a[i]  = As[kk][ty * 8 + i];
            #pragma unroll
            for (int j = 0; j < 8; ++j) bb[j] = Bs[kk][tx * 8 + j];
            #pragma unroll
            for (int i = 0; i < 8; ++i)
                #pragma unroll
                for (int j = 0; j < 8; ++j)
                    acc[i][j] += a[i] * bb[j];
        }
        __syncthreads();
    }
    #pragma unroll
    for (int i = 0; i < 8; ++i) {
        int row = m0 + ty * 8 + i;
        #pragma unroll
        for (int j = 0; j < 8; ++j) {
            int col = n0 + tx * 8 + j;
            float v = acc[i][j] + bias[col];
            if (HASRES) v += res[(size_t)row * Nn + col];
            if (RELU)   v = fmaxf(v, 0.f);
            C[(size_t)row * Nn + col] = v;
        }
    }
}

// ---------------------------------------------------------------------------
// Fused attention: one CTA per (g,h).  Scores for a 32-row chunk live in
// SMEM; edge bias comes from the CSR (shared atomics); softmax + PV + residual
// all in one pass.  k column for this thread lives in registers.
// SMEM: v[256][33] + q[32][33] + s[32][256]  = 70784 B
// ---------------------------------------------------------------------------
#define ATTN_SMEM ((256 * 33 + 32 * 33 + 32 * 256) * 4)

__global__ __launch_bounds__(256) void attn_kernel(
        const float* __restrict__ q, const float* __restrict__ k,
        const float* __restrict__ v, const float* __restrict__ x,
        float* __restrict__ xout) {
    extern __shared__ float sm[];
    float* vs = sm;                 // [256][33]
    float* qs = vs + 256 * 33;      // [32][33]
    float* s  = qs + 32 * 33;       // [32][256]

    int g = blockIdx.x >> 3;
    int h = blockIdx.x & 7;
    int tid = threadIdx.x;
    int base = g * N_;
    const float SCALE = 0.17677669529663687f;   // 1/sqrt(32)

    // this thread's k column (row m = tid of K block), in registers
    float kreg[32];
    {
        const float4* kr = (const float4*)(k + ((size_t)(base + tid)) * OUT_ + h * D_);
        #pragma unroll
        for (int i = 0; i < 8; ++i) {
            float4 f = kr[i];
            kreg[4 * i + 0] = f.x; kreg[4 * i + 1] = f.y;
            kreg[4 * i + 2] = f.z; kreg[4 * i + 3] = f.w;
        }
    }
    // cooperative, coalesced load of V tile into padded SMEM
    for (int idx = tid; idx < 256 * 32; idx += 256) {
        int d = idx & 31, r = idx >> 5;
        vs[r * 33 + d] = v[((size_t)(base + r)) * OUT_ + h * D_ + d];
    }
    __syncthreads();

    int w = tid >> 5, lane = tid & 31;

    for (int c = 0; c < 8; ++c) {               // 8 chunks of 32 query rows
        // load q chunk
        for (int idx = tid; idx < 32 * 32; idx += 256) {
            int d = idx & 31, r = idx >> 5;
            qs[r * 33 + d] = q[((size_t)(base + c * 32 + r)) * OUT_ + h * D_ + d];
        }
        __syncthreads();

        // scores: thread = key column tid, loop over 32 query rows
        #pragma unroll 4
        for (int r = 0; r < 32; ++r) {
            float acc = 0.f;
            #pragma unroll
            for (int d = 0; d < 32; ++d) acc += qs[r * 33 + d] * kreg[d];
            s[r * 256 + tid] = acc * SCALE;
        }
        __syncthreads();

        // edge bias from CSR: warp w handles rows 4w..4w+3
        #pragma unroll
        for (int rr = 0; rr < 4; ++rr) {
            int r = w * 4 + rr;
            int grow = base + c * 32 + r;
            int beg = g_rowptr[grow], end = g_rowptr[grow + 1];
            for (int j = beg + lane; j < end; j += 32)
                atomicAdd(&s[r * 256 + g_csr_dst[j]], g_ew[g_csr_eid[j] * H_ + h]);
        }
        __syncthreads();

        // softmax rows (warp per 4 rows)
        #pragma unroll
        for (int rr = 0; rr < 4; ++rr) {
            int r = w * 4 + rr;
            float vals[8];
            float mx = -1e30f;
            #pragma unroll
            for (int i = 0; i < 8; ++i) {
                vals[i] = s[r * 256 + lane + 32 * i];
                mx = fmaxf(mx, vals[i]);
            }
            mx = warp_max(mx);
            float sum = 0.f;
            #pragma unroll
            for (int i = 0; i < 8; ++i) { vals[i] = __expf(vals[i] - mx); sum += vals[i]; }
            sum = warp_sum(sum);
            float inv = __frcp_rn(sum);
            #pragma unroll
            for (int i = 0; i < 8; ++i) s[r * 256 + lane + 32 * i] = vals[i] * inv;
        }
        __syncthreads();

        // PV + residual: thread (d = tid&31, r0 = tid>>5) -> 4 outputs
        int d = tid & 31, r0 = tid >> 5;
        #pragma unroll
        for (int i = 0; i < 4; ++i) {
            int r = r0 + 8 * i;
            float acc = 0.f;
            #pragma unroll 8
            for (int m = 0; m < 256; ++m) acc += s[r * 256 + m] * vs[m * 33 + d];
            int grow = base + c * 32 + r;
            int col = h * D_ + d;
            xout[(size_t)grow * OUT_ + col] = x[(size_t)grow * OUT_ + col] + acc;
        }
        __syncthreads();
    }
}

// ---------------------------------------------------------------------------
// Launch
// ---------------------------------------------------------------------------
extern "C" void kernel_launch(void* const* d_in, const int* in_sizes, int n_in,
                              void* d_out, int out_size) {
    const float* x    = (const float*)d_in[0];
    const void*  ei   =                d_in[1];
    const float* ea   = (const float*)d_in[2];
    // d_in[3] = batch (unused)
    const float* ln1w = (const float*)d_in[4];
    const float* ln1b = (const float*)d_in[5];
    const float* Wq   = (const float*)d_in[6];
    const float* bq   = (const float*)d_in[7];
    const float* Wk   = (const float*)d_in[8];
    const float* bk   = (const float*)d_in[9];
    const float* Wv   = (const float*)d_in[10];
    const float* bv   = (const float*)d_in[11];
    const float* We   = (const float*)d_in[12];
    const float* be   = (const float*)d_in[13];
    const float* ln2w = (const float*)d_in[14];
    const float* ln2b = (const float*)d_in[15];
    const float* Wf1  = (const float*)d_in[16];
    const float* bf1  = (const float*)d_in[17];
    const float* Wf2  = (const float*)d_in[18];
    const float* bf2  = (const float*)d_in[19];
    float* out = (float*)d_out;

    // scratch pointers (symbol addresses; queries only, no allocation)
    float *p_xn, *p_q, *p_k, *p_v, *p_xout, *p_h, *p_ff1;
    cudaGetSymbolAddress((void**)&p_xn,   g_xn);
    cudaGetSymbolAddress((void**)&p_q,    g_q);
    cudaGetSymbolAddress((void**)&p_k,    g_k);
    cudaGetSymbolAddress((void**)&p_v,    g_v);
    cudaGetSymbolAddress((void**)&p_xout, g_xout);
    cudaGetSymbolAddress((void**)&p_h,    g_h);
    cudaGetSymbolAddress((void**)&p_ff1,  g_ff1);

    cudaFuncSetAttribute(attn_kernel,
                         cudaFuncAttributeMaxDynamicSharedMemorySize, ATTN_SMEM);

    // --- edge preprocessing (CSR + per-head edge bias) ---
    detect_kernel<<<1, 1>>>(ei);
    zero_counts_kernel<<<GN_ / 256, 256>>>();
    hist_kernel<<<E_ / 256, 256>>>(ei);
    scan_kernel<<<1, 1024>>>();
    scatter_kernel<<<E_ / 256, 256>>>(ei);
    ew_kernel<<<E_ / 256, 256>>>(ea, We, be);

    // --- LN1 + QKV projections ---
    ln_kernel<<<GN_ / 8, 256>>>(x, ln1w, ln1b, p_xn);
    dim3 g256(OUT_ / 128, GN_ / 128);
    gemm_kernel<false, false><<<g256, 256>>>(p_xn, Wq, bq, nullptr, p_q, GN_, OUT_, IN_);
    gemm_kernel<false, false><<<g256, 256>>>(p_xn, Wk, bk, nullptr, p_k, GN_, OUT_, IN_);
    gemm_kernel<false, false><<<g256, 256>>>(p_xn, Wv, bv, nullptr, p_v, GN_, OUT_, IN_);

    // --- fused attention (+ residual into xout) ---
    attn_kernel<<<G_ * H_, 256, ATTN_SMEM>>>(p_q, p_k, p_v, x, p_xout);

    // --- LN2 + FFN (+ residual) ---
    ln_kernel<<<GN_ / 8, 256>>>(p_xout, ln2w, ln2b, p_h);
    dim3 gff1(FF_ / 128, GN_ / 128);
    gemm_kernel<true, false><<<gff1, 256>>>(p_h, Wf1, bf1, nullptr, p_ff1, GN_, FF_, OUT_);
    gemm_kernel<false, true><<<g256, 256>>>(p_ff1, Wf2, bf2, p_xout, out, GN_, OUT_, FF_);
}

// round 5
// speedup vs baseline: 1.5988x; 1.5988x over previous
#include <cuda_runtime.h>
#include <cuda_bf16.h>
#include <cstdint>
#include <math.h>

// ---------------------------------------------------------------------------
// Problem constants
// ---------------------------------------------------------------------------
#define G_   64
#define N_   256
#define GN_  (G_ * N_)        // 16384 nodes
#define H_   8
#define D_   32
#define IN_  256
#define OUT_ 256
#define FF_  1024
#define E_   (GN_ * 16)       // 262144 edges
#define EPS_ 1e-5f

// ---------------------------------------------------------------------------
// PTX helpers (sm_100 baseline: mma.sync + ldmatrix + cp.async)
// ---------------------------------------------------------------------------
__device__ __forceinline__ uint32_t smem_u32(const void* p) {
    uint32_t a;
    asm("{ .reg .u64 t; cvta.to.shared.u64 t, %1; cvt.u32.u64 %0, t; }" : "=r"(a) : "l"(p));
    return a;
}
#define CP_ASYNC16(dst, src) \
    asm volatile("cp.async.cg.shared.global [%0], [%1], 16;" :: "r"(dst), "l"(src))
#define CP_COMMIT() asm volatile("cp.async.commit_group;" ::: "memory")
#define CP_WAIT1()  asm volatile("cp.async.wait_group 1;" ::: "memory")
#define CP_WAIT0()  asm volatile("cp.async.wait_group 0;" ::: "memory")

__device__ __forceinline__ void ldsm_x4(uint32_t addr, uint32_t* r) {
    asm volatile("ldmatrix.sync.aligned.m8n8.x4.shared.b16 {%0,%1,%2,%3}, [%4];"
                 : "=r"(r[0]), "=r"(r[1]), "=r"(r[2]), "=r"(r[3]) : "r"(addr));
}
__device__ __forceinline__ void mma16816(float* d, const uint32_t* a,
                                         uint32_t b0, uint32_t b1) {
    asm volatile(
        "mma.sync.aligned.m16n8k16.row.col.f32.bf16.bf16.f32 "
        "{%0,%1,%2,%3}, {%4,%5,%6,%7}, {%8,%9}, {%0,%1,%2,%3};"
        : "+f"(d[0]), "+f"(d[1]), "+f"(d[2]), "+f"(d[3])
        : "r"(a[0]), "r"(a[1]), "r"(a[2]), "r"(a[3]), "r"(b0), "r"(b1));
}

// ---------------------------------------------------------------------------
// Device scratch
// ---------------------------------------------------------------------------
__device__ __nv_bfloat16 g_xn_hi [GN_ * IN_],  g_xn_lo [GN_ * IN_];
__device__ __nv_bfloat16 g_h_hi  [GN_ * OUT_], g_h_lo  [GN_ * OUT_];
__device__ __nv_bfloat16 g_ff1_hi[GN_ * FF_],  g_ff1_lo[GN_ * FF_];
__device__ __nv_bfloat16 g_wqT_hi [OUT_ * IN_], g_wqT_lo [OUT_ * IN_];
__device__ __nv_bfloat16 g_wkT_hi [OUT_ * IN_], g_wkT_lo [OUT_ * IN_];
__device__ __nv_bfloat16 g_wvT_hi [OUT_ * IN_], g_wvT_lo [OUT_ * IN_];
__device__ __nv_bfloat16 g_wf1T_hi[FF_ * OUT_], g_wf1T_lo[FF_ * OUT_];
__device__ __nv_bfloat16 g_wf2T_hi[OUT_ * FF_], g_wf2T_lo[OUT_ * FF_];

__device__ float g_q   [GN_ * OUT_];
__device__ float g_k   [GN_ * OUT_];
__device__ float g_v   [GN_ * OUT_];
__device__ float g_ew  [E_ * H_];
__device__ float g_xout[GN_ * OUT_];

__device__ __align__(16) int g_counts [GN_];
__device__ int g_rowptr [GN_ + 1];
__device__ int g_cursor [GN_];
__device__ int g_csr_dst[E_];
__device__ int g_csr_eid[E_];
__device__ int g_is64;

// ---------------------------------------------------------------------------
// small helpers
// ---------------------------------------------------------------------------
__device__ __forceinline__ long long load_idx(const void* p, int i) {
    if (g_is64) return ((const long long*)p)[i];
    return (long long)(((const int*)p)[i]);
}
__device__ __forceinline__ float warp_sum(float v) {
    #pragma unroll
    for (int o = 16; o > 0; o >>= 1) v += __shfl_xor_sync(0xffffffffu, v, o);
    return v;
}
__device__ __forceinline__ float warp_max(float v) {
    #pragma unroll
    for (int o = 16; o > 0; o >>= 1) v = fmaxf(v, __shfl_xor_sync(0xffffffffu, v, o));
    return v;
}

// ---------------------------------------------------------------------------
// edge_index dtype detect + CSR build
// ---------------------------------------------------------------------------
__global__ void detect_kernel(const void* __restrict__ ei) {
    __shared__ int bad;
    if (threadIdx.x == 0) bad = 0;
    __syncthreads();
    const long long* p = (const long long*)ei;
    long long v0 = p[threadIdx.x];
    long long v1 = p[256 + threadIdx.x];
    if (v0 < 0 || v0 >= GN_ || v1 < 0 || v1 >= GN_) atomicOr(&bad, 1);
    __syncthreads();
    if (threadIdx.x == 0) g_is64 = !bad;
}
__global__ void zero_counts_kernel() {
    g_counts[blockIdx.x * 256 + threadIdx.x] = 0;
}
__global__ void hist_kernel(const void* __restrict__ ei) {
    int e = blockIdx.x * 256 + threadIdx.x;
    atomicAdd(&g_counts[(int)load_idx(ei, e)], 1);
}
__global__ void scan_kernel() {
    __shared__ int wsum[32];
    int t = threadIdx.x;
    int base = t * 16;
    int local[16];
    #pragma unroll
    for (int q = 0; q < 4; ++q)
        *(int4*)(local + 4 * q) = *(const int4*)(g_counts + base + 4 * q);
    int s = 0;
    #pragma unroll
    for (int i = 0; i < 16; ++i) s += local[i];
    int lane = t & 31, w = t >> 5;
    int inc = s;
    #pragma unroll
    for (int o = 1; o < 32; o <<= 1) {
        int n = __shfl_up_sync(0xffffffffu, inc, o);
        if (lane >= o) inc += n;
    }
    if (lane == 31) wsum[w] = inc;
    __syncthreads();
    if (w == 0) {
        int v = wsum[lane];
        #pragma unroll
        for (int o = 1; o < 32; o <<= 1) {
            int n = __shfl_up_sync(0xffffffffu, v, o);
            if (lane >= o) v += n;
        }
        wsum[lane] = v;
    }
    __syncthreads();
    int run = inc - s + (w > 0 ? wsum[w - 1] : 0);
    #pragma unroll
    for (int i = 0; i < 16; ++i) {
        g_rowptr[base + i] = run;
        g_cursor[base + i] = run;
        run += local[i];
    }
    if (t == 1023) g_rowptr[GN_] = run;
}
__global__ void scatter_kernel(const void* __restrict__ ei) {
    int e = blockIdx.x * 256 + threadIdx.x;
    int src = (int)load_idx(ei, e);
    int dst = (int)load_idx(ei, E_ + e);
    int pos = atomicAdd(&g_cursor[src], 1);
    g_csr_dst[pos] = dst & (N_ - 1);
    g_csr_eid[pos] = e;
}
__global__ void ew_kernel(const float* __restrict__ ea,
                          const float* __restrict__ We,
                          const float* __restrict__ be) {
    int e = blockIdx.x * 256 + threadIdx.x;
    float a0 = ea[2 * e], a1 = ea[2 * e + 1];
    #pragma unroll
    for (int h = 0; h < H_; ++h)
        g_ew[e * H_ + h] = a0 * We[h] + a1 * We[H_ + h] + be[h];
}

// ---------------------------------------------------------------------------
// Weight prep: W[K,N] fp32 -> WT[N,K] bf16 hi/lo (32x32 smem transpose)
// ---------------------------------------------------------------------------
__global__ void wprep_kernel(const float* __restrict__ W,
                             __nv_bfloat16* __restrict__ Thi,
                             __nv_bfloat16* __restrict__ Tlo, int K, int Nn) {
    __shared__ float t[32][33];
    int k0 = blockIdx.x * 32, n0 = blockIdx.y * 32;
    int tx = threadIdx.x, ty = threadIdx.y;
    for (int i = ty; i < 32; i += 8)
        t[i][tx] = W[(size_t)(k0 + i) * Nn + n0 + tx];
    __syncthreads();
    for (int i = ty; i < 32; i += 8) {
        float v = t[tx][i];
        __nv_bfloat16 h = __float2bfloat16(v);
        size_t o = (size_t)(n0 + i) * K + k0 + tx;
        Thi[o] = h;
        Tlo[o] = __float2bfloat16(v - __bfloat162float(h));
    }
}

// ---------------------------------------------------------------------------
// LayerNorm -> bf16 hi/lo split output
// ---------------------------------------------------------------------------
__global__ __launch_bounds__(256) void ln_split_kernel(
        const float* __restrict__ x, const float* __restrict__ w,
        const float* __restrict__ b,
        __nv_bfloat16* __restrict__ ohi, __nv_bfloat16* __restrict__ olo) {
    int row  = blockIdx.x * 8 + (threadIdx.x >> 5);
    int lane = threadIdx.x & 31;
    const float* xr = x + (size_t)row * 256;
    float v[8];
    float s = 0.f;
    #pragma unroll
    for (int i = 0; i < 8; ++i) { v[i] = xr[lane + 32 * i]; s += v[i]; }
    s = warp_sum(s);
    float mean = s * (1.f / 256.f);
    float sq = 0.f;
    #pragma unroll
    for (int i = 0; i < 8; ++i) { float d = v[i] - mean; sq += d * d; }
    sq = warp_sum(sq);
    float rstd = rsqrtf(sq * (1.f / 256.f) + EPS_);
    #pragma unroll
    for (int i = 0; i < 8; ++i) {
        int c = lane + 32 * i;
        float y = (v[i] - mean) * rstd * w[c] + b[c];
        __nv_bfloat16 h = __float2bfloat16(y);
        ohi[(size_t)row * 256 + c] = h;
        olo[(size_t)row * 256 + c] = __float2bfloat16(y - __bfloat162float(h));
    }
}

// ---------------------------------------------------------------------------
// mma.sync GEMM core.  C[128,128] tile = A @ B^T with split-bf16 (3 products).
// A: [M,K] bf16 hi/lo row-major.  B: [Nn,K] bf16 hi/lo (pre-transposed).
// K-chunks of 64 (128B rows, xor swizzle), cp.async double buffer.
// 8 warps: 4(M) x 2(N), warp tile 32x64.
// MODE 0: fp32+bias; 1: relu+bias -> bf16 hi/lo; 2: fp32+bias+residual.
// ---------------------------------------------------------------------------
#define STAGE_SZ 65536
#define OFF_AHI  0
#define OFF_ALO  16384
#define OFF_BHI  32768
#define OFF_BLO  49152
#define GEMM_SMEM (2 * STAGE_SZ)

__device__ __forceinline__ void g2s_stage(uint32_t sbase,
        const __nv_bfloat16* __restrict__ Ahi, const __nv_bfloat16* __restrict__ Alo,
        const __nv_bfloat16* __restrict__ Bhi, const __nv_bfloat16* __restrict__ Blo,
        int K, int m0, int n0, int kc, int tid) {
    size_t kb = (size_t)kc * 64;
    #pragma unroll
    for (int l = 0; l < 4; ++l) {
        int idx = tid + l * 256;          // 1024 16B-chunks: row = idx/8, cb = idx%8
        int r = idx >> 3, cb = idx & 7;
        uint32_t doff = (r << 7) + ((cb ^ (r & 7)) << 4);
        const char* a_src = (const char*)(Ahi + (size_t)(m0 + r) * K + kb) + cb * 16;
        const char* al_src = (const char*)(Alo + (size_t)(m0 + r) * K + kb) + cb * 16;
        const char* b_src = (const char*)(Bhi + (size_t)(n0 + r) * K + kb) + cb * 16;
        const char* bl_src = (const char*)(Blo + (size_t)(n0 + r) * K + kb) + cb * 16;
        CP_ASYNC16(sbase + OFF_AHI + doff, a_src);
        CP_ASYNC16(sbase + OFF_ALO + doff, al_src);
        CP_ASYNC16(sbase + OFF_BHI + doff, b_src);
        CP_ASYNC16(sbase + OFF_BLO + doff, bl_src);
    }
}

template <int MODE>
__device__ __forceinline__ void gemm_core(
        const __nv_bfloat16* __restrict__ Ahi, const __nv_bfloat16* __restrict__ Alo,
        const __nv_bfloat16* __restrict__ Bhi, const __nv_bfloat16* __restrict__ Blo,
        int K, const float* __restrict__ bias, const float* __restrict__ res,
        float* __restrict__ outf,
        __nv_bfloat16* __restrict__ outhi, __nv_bfloat16* __restrict__ outlo,
        int m0, int n0, int ldc) {
    extern __shared__ char dynsmem[];
    uint32_t sb = smem_u32(dynsmem);
    const int tid  = threadIdx.x;
    const int lane = tid & 31;
    const int wid  = tid >> 5;
    const int wm   = wid & 3;             // 0..3 -> M offset 32*wm
    const int wn   = wid >> 2;            // 0..1 -> N offset 64*wn

    // per-lane ldmatrix row/col decomposition
    const int a_r   = (lane & 7) + ((lane >> 3) & 1) * 8;  // row in m16
    const int a_cb0 = lane >> 4;                           // k 8-block (0/1)
    const int b_r   = (lane & 7) + ((lane >> 4) << 3);     // row in n16 pair
    const int b_cb0 = (lane >> 3) & 1;

    float acc[2][8][4];
    #pragma unroll
    for (int i = 0; i < 2; ++i)
        #pragma unroll
        for (int j = 0; j < 8; ++j)
            #pragma unroll
            for (int q = 0; q < 4; ++q) acc[i][j][q] = 0.f;

    const int nc = K >> 6;
    g2s_stage(sb, Ahi, Alo, Bhi, Blo, K, m0, n0, 0, tid);
    CP_COMMIT();

    for (int c = 0; c < nc; ++c) {
        if (c + 1 < nc) {
            g2s_stage(sb + ((c + 1) & 1) * STAGE_SZ, Ahi, Alo, Bhi, Blo, K, m0, n0, c + 1, tid);
            CP_COMMIT();
            CP_WAIT1();
        } else {
            CP_WAIT0();
        }
        __syncthreads();

        uint32_t stg = sb + (c & 1) * STAGE_SZ;
        #pragma unroll
        for (int ks = 0; ks < 4; ++ks) {
            uint32_t ah[2][4], al[2][4], bh[4][4], bl[4][4];
            #pragma unroll
            for (int mt = 0; mt < 2; ++mt) {
                int row = wm * 32 + mt * 16 + a_r;
                int cb  = ks * 2 + a_cb0;
                uint32_t off = (row << 7) + (((cb) ^ (row & 7)) << 4);
                ldsm_x4(stg + OFF_AHI + off, ah[mt]);
                ldsm_x4(stg + OFF_ALO + off, al[mt]);
            }
            #pragma unroll
            for (int bt = 0; bt < 4; ++bt) {
                int row = wn * 64 + bt * 16 + b_r;
                int cb  = ks * 2 + b_cb0;
                uint32_t off = (row << 7) + (((cb) ^ (row & 7)) << 4);
                ldsm_x4(stg + OFF_BHI + off, bh[bt]);
                ldsm_x4(stg + OFF_BLO + off, bl[bt]);
            }
            #pragma unroll
            for (int mt = 0; mt < 2; ++mt)
                #pragma unroll
                for (int nt = 0; nt < 8; ++nt) {
                    int bt = nt >> 1, hf = (nt & 1) * 2;
                    mma16816(acc[mt][nt], ah[mt], bh[bt][hf], bh[bt][hf + 1]); // hi*hi
                    mma16816(acc[mt][nt], ah[mt], bl[bt][hf], bl[bt][hf + 1]); // hi*lo
                    mma16816(acc[mt][nt], al[mt], bh[bt][hf], bh[bt][hf + 1]); // lo*hi
                }
        }
        __syncthreads();
    }

    // epilogue
    const int gid = lane >> 2, tig = lane & 3;
    #pragma unroll
    for (int mt = 0; mt < 2; ++mt) {
        int m = m0 + wm * 32 + mt * 16 + gid;
        #pragma unroll
        for (int nt = 0; nt < 8; ++nt) {
            int n = n0 + wn * 64 + nt * 8 + tig * 2;
            float* a = acc[mt][nt];
            float b0 = bias[n], b1 = bias[n + 1];
            if (MODE == 0) {
                float2 v0 = make_float2(a[0] + b0, a[1] + b1);
                float2 v1 = make_float2(a[2] + b0, a[3] + b1);
                *(float2*)(outf + (size_t)m * ldc + n) = v0;
                *(float2*)(outf + (size_t)(m + 8) * ldc + n) = v1;
            } else if (MODE == 1) {
                float v00 = fmaxf(a[0] + b0, 0.f), v01 = fmaxf(a[1] + b1, 0.f);
                float v10 = fmaxf(a[2] + b0, 0.f), v11 = fmaxf(a[3] + b1, 0.f);
                __nv_bfloat162 h0, l0, h1, l1;
                h0.x = __float2bfloat16(v00); h0.y = __float2bfloat16(v01);
                l0.x = __float2bfloat16(v00 - __bfloat162float(h0.x));
                l0.y = __float2bfloat16(v01 - __bfloat162float(h0.y));
                h1.x = __float2bfloat16(v10); h1.y = __float2bfloat16(v11);
                l1.x = __float2bfloat16(v10 - __bfloat162float(h1.x));
                l1.y = __float2bfloat16(v11 - __bfloat162float(h1.y));
                *(__nv_bfloat162*)(outhi + (size_t)m * ldc + n) = h0;
                *(__nv_bfloat162*)(outlo + (size_t)m * ldc + n) = l0;
                *(__nv_bfloat162*)(outhi + (size_t)(m + 8) * ldc + n) = h1;
                *(__nv_bfloat162*)(outlo + (size_t)(m + 8) * ldc + n) = l1;
            } else {
                float2 r0 = *(const float2*)(res + (size_t)m * ldc + n);
                float2 r1 = *(const float2*)(res + (size_t)(m + 8) * ldc + n);
                float2 v0 = make_float2(a[0] + b0 + r0.x, a[1] + b1 + r0.y);
                float2 v1 = make_float2(a[2] + b0 + r1.x, a[3] + b1 + r1.y);
                *(float2*)(outf + (size_t)m * ldc + n) = v0;
                *(float2*)(outf + (size_t)(m + 8) * ldc + n) = v1;
            }
        }
    }
}

__global__ __launch_bounds__(256, 1) void qkv_kernel(const float* bq, const float* bk, const float* bv) {
    const __nv_bfloat16 *Bh, *Bl;
    const float* bias;
    float* out;
    if (blockIdx.z == 0)      { Bh = g_wqT_hi; Bl = g_wqT_lo; bias = bq; out = g_q; }
    else if (blockIdx.z == 1) { Bh = g_wkT_hi; Bl = g_wkT_lo; bias = bk; out = g_k; }
    else                      { Bh = g_wvT_hi; Bl = g_wvT_lo; bias = bv; out = g_v; }
    gemm_core<0>(g_xn_hi, g_xn_lo, Bh, Bl, 256, bias, nullptr,
                 out, nullptr, nullptr, blockIdx.x * 128, blockIdx.y * 128, 256);
}
__global__ __launch_bounds__(256, 1) void ff1_kernel(const float* bf1) {
    gemm_core<1>(g_h_hi, g_h_lo, g_wf1T_hi, g_wf1T_lo, 256, bf1, nullptr,
                 nullptr, g_ff1_hi, g_ff1_lo, blockIdx.x * 128, blockIdx.y * 128, 1024);
}
__global__ __launch_bounds__(256, 1) void ff2_kernel(const float* bf2, float* out) {
    gemm_core<2>(g_ff1_hi, g_ff1_lo, g_wf2T_hi, g_wf2T_lo, 1024, bf2, g_xout,
                 out, nullptr, nullptr, blockIdx.x * 128, blockIdx.y * 128, 256);
}

// ---------------------------------------------------------------------------
// Fused attention (known-good from round 1)
// ---------------------------------------------------------------------------
#define ATTN_SMEM ((256 * 33 + 32 * 33 + 32 * 256) * 4)

__global__ __launch_bounds__(256) void attn_kernel(
        const float* __restrict__ q, const float* __restrict__ k,
        const float* __restrict__ v, const float* __restrict__ x,
        float* __restrict__ xout) {
    extern __shared__ float sm[];
    float* vs = sm;
    float* qs = vs + 256 * 33;
    float* s  = qs + 32 * 33;

    int g = blockIdx.x >> 3;
    int h = blockIdx.x & 7;
    int tid = threadIdx.x;
    int base = g * N_;
    const float SCALE = 0.17677669529663687f;

    float kreg[32];
    {
        const float4* kr = (const float4*)(k + ((size_t)(base + tid)) * OUT_ + h * D_);
        #pragma unroll
        for (int i = 0; i < 8; ++i) {
            float4 f = kr[i];
            kreg[4 * i + 0] = f.x; kreg[4 * i + 1] = f.y;
            kreg[4 * i + 2] = f.z; kreg[4 * i + 3] = f.w;
        }
    }
    for (int idx = tid; idx < 256 * 32; idx += 256) {
        int d = idx & 31, r = idx >> 5;
        vs[r * 33 + d] = v[((size_t)(base + r)) * OUT_ + h * D_ + d];
    }
    __syncthreads();

    int w = tid >> 5, lane = tid & 31;

    for (int c = 0; c < 8; ++c) {
        for (int idx = tid; idx < 32 * 32; idx += 256) {
            int d = idx & 31, r = idx >> 5;
            qs[r * 33 + d] = q[((size_t)(base + c * 32 + r)) * OUT_ + h * D_ + d];
        }
        __syncthreads();

        #pragma unroll 4
        for (int r = 0; r < 32; ++r) {
            float acc = 0.f;
            #pragma unroll
            for (int d = 0; d < 32; ++d) acc += qs[r * 33 + d] * kreg[d];
            s[r * 256 + tid] = acc * SCALE;
        }
        __syncthreads();

        #pragma unroll
        for (int rr = 0; rr < 4; ++rr) {
            int r = w * 4 + rr;
            int grow = base + c * 32 + r;
            int beg = g_rowptr[grow], end = g_rowptr[grow + 1];
            for (int j = beg + lane; j < end; j += 32)
                atomicAdd(&s[r * 256 + g_csr_dst[j]], g_ew[g_csr_eid[j] * H_ + h]);
        }
        __syncthreads();

        #pragma unroll
        for (int rr = 0; rr < 4; ++rr) {
            int r = w * 4 + rr;
            float vals[8];
            float mx = -1e30f;
            #pragma unroll
            for (int i = 0; i < 8; ++i) {
                vals[i] = s[r * 256 + lane + 32 * i];
                mx = fmaxf(mx, vals[i]);
            }
            mx = warp_max(mx);
            float sum = 0.f;
            #pragma unroll
            for (int i = 0; i < 8; ++i) { vals[i] = __expf(vals[i] - mx); sum += vals[i]; }
            sum = warp_sum(sum);
            float inv = __frcp_rn(sum);
            #pragma unroll
            for (int i = 0; i < 8; ++i) s[r * 256 + lane + 32 * i] = vals[i] * inv;
        }
        __syncthreads();

        int d = tid & 31, r0 = tid >> 5;
        #pragma unroll
        for (int i = 0; i < 4; ++i) {
            int r = r0 + 8 * i;
            float acc = 0.f;
            #pragma unroll 8
            for (int m = 0; m < 256; ++m) acc += s[r * 256 + m] * vs[m * 33 + d];
            int grow = base + c * 32 + r;
            int col = h * D_ + d;
            xout[(size_t)grow * OUT_ + col] = x[(size_t)grow * OUT_ + col] + acc;
        }
        __syncthreads();
    }
}

// ---------------------------------------------------------------------------
// Launch
// ---------------------------------------------------------------------------
extern "C" void kernel_launch(void* const* d_in, const int* in_sizes, int n_in,
                              void* d_out, int out_size) {
    const float* x    = (const float*)d_in[0];
    const void*  ei   =                d_in[1];
    const float* ea   = (const float*)d_in[2];
    const float* ln1w = (const float*)d_in[4];
    const float* ln1b = (const float*)d_in[5];
    const float* Wq   = (const float*)d_in[6];
    const float* bq   = (const float*)d_in[7];
    const float* Wk   = (const float*)d_in[8];
    const float* bk   = (const float*)d_in[9];
    const float* Wv   = (const float*)d_in[10];
    const float* bv   = (const float*)d_in[11];
    const float* We   = (const float*)d_in[12];
    const float* be   = (const float*)d_in[13];
    const float* ln2w = (const float*)d_in[14];
    const float* ln2b = (const float*)d_in[15];
    const float* Wf1  = (const float*)d_in[16];
    const float* bf1  = (const float*)d_in[17];
    const float* Wf2  = (const float*)d_in[18];
    const float* bf2  = (const float*)d_in[19];
    float* out = (float*)d_out;

    float *p_q, *p_k, *p_v, *p_xout;
    __nv_bfloat16 *p_xnh, *p_xnl, *p_hh, *p_hl;
    __nv_bfloat16 *p_wq_h, *p_wq_l, *p_wk_h, *p_wk_l, *p_wv_h, *p_wv_l;
    __nv_bfloat16 *p_w1_h, *p_w1_l, *p_w2_h, *p_w2_l;
    cudaGetSymbolAddress((void**)&p_q,    g_q);
    cudaGetSymbolAddress((void**)&p_k,    g_k);
    cudaGetSymbolAddress((void**)&p_v,    g_v);
    cudaGetSymbolAddress((void**)&p_xout, g_xout);
    cudaGetSymbolAddress((void**)&p_xnh,  g_xn_hi);
    cudaGetSymbolAddress((void**)&p_xnl,  g_xn_lo);
    cudaGetSymbolAddress((void**)&p_hh,   g_h_hi);
    cudaGetSymbolAddress((void**)&p_hl,   g_h_lo);
    cudaGetSymbolAddress((void**)&p_wq_h, g_wqT_hi);
    cudaGetSymbolAddress((void**)&p_wq_l, g_wqT_lo);
    cudaGetSymbolAddress((void**)&p_wk_h, g_wkT_hi);
    cudaGetSymbolAddress((void**)&p_wk_l, g_wkT_lo);
    cudaGetSymbolAddress((void**)&p_wv_h, g_wvT_hi);
    cudaGetSymbolAddress((void**)&p_wv_l, g_wvT_lo);
    cudaGetSymbolAddress((void**)&p_w1_h, g_wf1T_hi);
    cudaGetSymbolAddress((void**)&p_w1_l, g_wf1T_lo);
    cudaGetSymbolAddress((void**)&p_w2_h, g_wf2T_hi);
    cudaGetSymbolAddress((void**)&p_w2_l, g_wf2T_lo);

    cudaFuncSetAttribute(attn_kernel, cudaFuncAttributeMaxDynamicSharedMemorySize, ATTN_SMEM);
    cudaFuncSetAttribute(qkv_kernel,  cudaFuncAttributeMaxDynamicSharedMemorySize, GEMM_SMEM);
    cudaFuncSetAttribute(ff1_kernel,  cudaFuncAttributeMaxDynamicSharedMemorySize, GEMM_SMEM);
    cudaFuncSetAttribute(ff2_kernel,  cudaFuncAttributeMaxDynamicSharedMemorySize, GEMM_SMEM);

    // --- edge preprocessing ---
    detect_kernel<<<1, 256>>>(ei);
    zero_counts_kernel<<<GN_ / 256, 256>>>();
    hist_kernel<<<E_ / 256, 256>>>(ei);
    scan_kernel<<<1, 1024>>>();
    scatter_kernel<<<E_ / 256, 256>>>(ei);
    ew_kernel<<<E_ / 256, 256>>>(ea, We, be);

    // --- weight prep (transpose + bf16 split) ---
    dim3 wb(32, 8);
    wprep_kernel<<<dim3(IN_ / 32, OUT_ / 32), wb>>>(Wq,  p_wq_h, p_wq_l, IN_,  OUT_);
    wprep_kernel<<<dim3(IN_ / 32, OUT_ / 32), wb>>>(Wk,  p_wk_h, p_wk_l, IN_,  OUT_);
    wprep_kernel<<<dim3(IN_ / 32, OUT_ / 32), wb>>>(Wv,  p_wv_h, p_wv_l, IN_,  OUT_);
    wprep_kernel<<<dim3(OUT_ / 32, FF_ / 32), wb>>>(Wf1, p_w1_h, p_w1_l, OUT_, FF_);
    wprep_kernel<<<dim3(FF_ / 32, OUT_ / 32), wb>>>(Wf2, p_w2_h, p_w2_l, FF_,  OUT_);

    // --- LN1 + QKV ---
    ln_split_kernel<<<GN_ / 8, 256>>>(x, ln1w, ln1b, p_xnh, p_xnl);
    qkv_kernel<<<dim3(GN_ / 128, OUT_ / 128, 3), 256, GEMM_SMEM>>>(bq, bk, bv);

    // --- attention (+ residual) ---
    attn_kernel<<<G_ * H_, 256, ATTN_SMEM>>>(p_q, p_k, p_v, x, p_xout);

    // --- LN2 + FFN ---
    ln_split_kernel<<<GN_ / 8, 256>>>(p_xout, ln2w, ln2b, p_hh, p_hl);
    ff1_kernel<<<dim3(GN_ / 128, FF_ / 128), 256, GEMM_SMEM>>>(bf1);
    ff2_kernel<<<dim3(GN_ / 128, OUT_ / 128), 256, GEMM_SMEM>>>(bf2, out);
}

// round 6
// speedup vs baseline: 2.0251x; 1.2667x over previous
#include <cuda_runtime.h>
#include <cuda_bf16.h>
#include <cstdint>
#include <math.h>

// ---------------------------------------------------------------------------
// Problem constants
// ---------------------------------------------------------------------------
#define G_   64
#define N_   256
#define GN_  (G_ * N_)        // 16384 nodes
#define H_   8
#define D_   32
#define IN_  256
#define OUT_ 256
#define FF_  1024
#define E_   (GN_ * 16)       // 262144 edges
#define EPS_ 1e-5f
#define QSCALE 0.17677669529663687f   // 1/sqrt(32)
#define DEG_CAP 64

// ---------------------------------------------------------------------------
// PTX helpers (sm_100 baseline: mma.sync + ldmatrix + cp.async)
// ---------------------------------------------------------------------------
__device__ __forceinline__ uint32_t smem_u32(const void* p) {
    uint32_t a;
    asm("{ .reg .u64 t; cvta.to.shared.u64 t, %1; cvt.u32.u64 %0, t; }" : "=r"(a) : "l"(p));
    return a;
}
#define CP_ASYNC16(dst, src) \
    asm volatile("cp.async.cg.shared.global [%0], [%1], 16;" :: "r"(dst), "l"(src))
#define CP_COMMIT() asm volatile("cp.async.commit_group;" ::: "memory")
#define CP_WAIT1()  asm volatile("cp.async.wait_group 1;" ::: "memory")
#define CP_WAIT0()  asm volatile("cp.async.wait_group 0;" ::: "memory")

__device__ __forceinline__ void ldsm_x4(uint32_t addr, uint32_t* r) {
    asm volatile("ldmatrix.sync.aligned.m8n8.x4.shared.b16 {%0,%1,%2,%3}, [%4];"
                 : "=r"(r[0]), "=r"(r[1]), "=r"(r[2]), "=r"(r[3]) : "r"(addr));
}
__device__ __forceinline__ void mma16816(float* d, const uint32_t* a,
                                         uint32_t b0, uint32_t b1) {
    asm volatile(
        "mma.sync.aligned.m16n8k16.row.col.f32.bf16.bf16.f32 "
        "{%0,%1,%2,%3}, {%4,%5,%6,%7}, {%8,%9}, {%0,%1,%2,%3};"
        : "+f"(d[0]), "+f"(d[1]), "+f"(d[2]), "+f"(d[3])
        : "r"(a[0]), "r"(a[1]), "r"(a[2]), "r"(a[3]), "r"(b0), "r"(b1));
}
__device__ __forceinline__ uint32_t pack_bf2(float a, float b) {
    __nv_bfloat162 t;
    t.x = __float2bfloat16(a);
    t.y = __float2bfloat16(b);
    return *(uint32_t*)&t;
}

// ---------------------------------------------------------------------------
// Device scratch
// ---------------------------------------------------------------------------
__device__ __nv_bfloat16 g_xn_hi [GN_ * IN_],  g_xn_lo [GN_ * IN_];
__device__ __nv_bfloat16 g_h_hi  [GN_ * OUT_], g_h_lo  [GN_ * OUT_];
__device__ __nv_bfloat16 g_ff1_hi[GN_ * FF_],  g_ff1_lo[GN_ * FF_];
__device__ __nv_bfloat16 g_wqT_hi [OUT_ * IN_], g_wqT_lo [OUT_ * IN_];
__device__ __nv_bfloat16 g_wkT_hi [OUT_ * IN_], g_wkT_lo [OUT_ * IN_];
__device__ __nv_bfloat16 g_wvT_hi [OUT_ * IN_], g_wvT_lo [OUT_ * IN_];
__device__ __nv_bfloat16 g_wf1T_hi[FF_ * OUT_], g_wf1T_lo[FF_ * OUT_];
__device__ __nv_bfloat16 g_wf2T_hi[OUT_ * FF_], g_wf2T_lo[OUT_ * FF_];

// attention-ready buffers (pre-swizzled smem images, written by QKV epilogue)
// q/k: per (g,h): 256 rows x 128B (hi d0..31 | lo d0..31), SW128 xor swizzle
// vT : per (g,h): 32 rows (d) x 1024B (hi t0..255 | lo t0..255), xor swizzle
__device__ __align__(128) char g_qa[512 * 32768];
__device__ __align__(128) char g_ka[512 * 32768];
__device__ __align__(128) char g_va[512 * 32768];

__device__ float g_ew  [E_ * H_];
__device__ float g_xout[GN_ * OUT_];

__device__ int      g_cnt[GN_];
__device__ uint32_t g_adj[GN_ * DEG_CAP];   // (eid << 8) | local_dst
__device__ int      g_is64;

// ---------------------------------------------------------------------------
// small helpers
// ---------------------------------------------------------------------------
__device__ __forceinline__ long long load_idx(const void* p, int i) {
    if (g_is64) return ((const long long*)p)[i];
    return (long long)(((const int*)p)[i]);
}
__device__ __forceinline__ float warp_sum(float v) {
    #pragma unroll
    for (int o = 16; o > 0; o >>= 1) v += __shfl_xor_sync(0xffffffffu, v, o);
    return v;
}
__device__ __forceinline__ float warp_max(float v) {
    #pragma unroll
    for (int o = 16; o > 0; o >>= 1) v = fmaxf(v, __shfl_xor_sync(0xffffffffu, v, o));
    return v;
}

// ---------------------------------------------------------------------------
// prep: dtype detect + zero counters (1 kernel), scatter + edge weights (1)
// ---------------------------------------------------------------------------
__global__ void detect_zero_kernel(const void* __restrict__ ei) {
    int i = blockIdx.x * 256 + threadIdx.x;
    g_cnt[i] = 0;
    if (blockIdx.x == 0) {
        __shared__ int bad;
        if (threadIdx.x == 0) bad = 0;
        __syncthreads();
        const long long* p = (const long long*)ei;
        long long v0 = p[threadIdx.x];
        long long v1 = p[256 + threadIdx.x];
        if (v0 < 0 || v0 >= GN_ || v1 < 0 || v1 >= GN_) atomicOr(&bad, 1);
        __syncthreads();
        if (threadIdx.x == 0) g_is64 = !bad;
    }
}
__global__ void scatter_ew_kernel(const void* __restrict__ ei,
                                  const float* __restrict__ ea,
                                  const float* __restrict__ We,
                                  const float* __restrict__ be) {
    int e = blockIdx.x * 256 + threadIdx.x;
    int src = (int)load_idx(ei, e);
    int dst = (int)load_idx(ei, E_ + e);
    int slot = atomicAdd(&g_cnt[src], 1);
    if (slot < DEG_CAP)
        g_adj[src * DEG_CAP + slot] = ((uint32_t)e << 8) | (uint32_t)(dst & (N_ - 1));
    float a0 = ea[2 * e], a1 = ea[2 * e + 1];
    #pragma unroll
    for (int h = 0; h < H_; ++h)
        g_ew[e * H_ + h] = a0 * We[h] + a1 * We[H_ + h] + be[h];
}

// ---------------------------------------------------------------------------
// Weight prep: all 5 matrices in one launch.  W[K,N] fp32 -> WT[N,K] hi/lo.
// ---------------------------------------------------------------------------
__global__ void wprep_all_kernel(const float* Wq, const float* Wk, const float* Wv,
                                 const float* Wf1, const float* Wf2) {
    __shared__ float t[32][33];
    int b = blockIdx.x;
    const float* W;
    __nv_bfloat16 *Th, *Tl;
    int K, Nn, tI;
    if (b < 64)       { W = Wq;  Th = g_wqT_hi;  Tl = g_wqT_lo;  K = IN_;  Nn = OUT_; tI = b; }
    else if (b < 128) { W = Wk;  Th = g_wkT_hi;  Tl = g_wkT_lo;  K = IN_;  Nn = OUT_; tI = b - 64; }
    else if (b < 192) { W = Wv;  Th = g_wvT_hi;  Tl = g_wvT_lo;  K = IN_;  Nn = OUT_; tI = b - 128; }
    else if (b < 448) { W = Wf1; Th = g_wf1T_hi; Tl = g_wf1T_lo; K = OUT_; Nn = FF_;  tI = b - 192; }
    else              { W = Wf2; Th = g_wf2T_hi; Tl = g_wf2T_lo; K = FF_;  Nn = OUT_; tI = b - 448; }
    int kt = K / 32;
    int k0 = (tI % kt) * 32, n0 = (tI / kt) * 32;
    int tx = threadIdx.x, ty = threadIdx.y;
    for (int i = ty; i < 32; i += 8)
        t[i][tx] = W[(size_t)(k0 + i) * Nn + n0 + tx];
    __syncthreads();
    for (int i = ty; i < 32; i += 8) {
        float v = t[tx][i];
        __nv_bfloat16 h = __float2bfloat16(v);
        size_t o = (size_t)(n0 + i) * K + k0 + tx;
        Th[o] = h;
        Tl[o] = __float2bfloat16(v - __bfloat162float(h));
    }
}

// ---------------------------------------------------------------------------
// LayerNorm -> bf16 hi/lo split output
// ---------------------------------------------------------------------------
__global__ __launch_bounds__(256) void ln_split_kernel(
        const float* __restrict__ x, const float* __restrict__ w,
        const float* __restrict__ b,
        __nv_bfloat16* __restrict__ ohi, __nv_bfloat16* __restrict__ olo) {
    int row  = blockIdx.x * 8 + (threadIdx.x >> 5);
    int lane = threadIdx.x & 31;
    const float* xr = x + (size_t)row * 256;
    float v[8];
    float s = 0.f;
    #pragma unroll
    for (int i = 0; i < 8; ++i) { v[i] = xr[lane + 32 * i]; s += v[i]; }
    s = warp_sum(s);
    float mean = s * (1.f / 256.f);
    float sq = 0.f;
    #pragma unroll
    for (int i = 0; i < 8; ++i) { float d = v[i] - mean; sq += d * d; }
    sq = warp_sum(sq);
    float rstd = rsqrtf(sq * (1.f / 256.f) + EPS_);
    #pragma unroll
    for (int i = 0; i < 8; ++i) {
        int c = lane + 32 * i;
        float y = (v[i] - mean) * rstd * w[c] + b[c];
        __nv_bfloat16 h = __float2bfloat16(y);
        ohi[(size_t)row * 256 + c] = h;
        olo[(size_t)row * 256 + c] = __float2bfloat16(y - __bfloat162float(h));
    }
}

// ---------------------------------------------------------------------------
// mma.sync GEMM core (proven round-5).  C tile 128x128, split-bf16 3 products.
// MODE 1: relu+bias -> bf16 hi/lo; MODE 2: fp32+bias+residual;
// MODE 3: qkv -> attention-layout bf16 hi/lo buffers (zkind 0=q,1=k,2=v).
// ---------------------------------------------------------------------------
#define STAGE_SZ 65536
#define OFF_AHI  0
#define OFF_ALO  16384
#define OFF_BHI  32768
#define OFF_BLO  49152
#define GEMM_SMEM (2 * STAGE_SZ)

__device__ __forceinline__ void g2s_stage(uint32_t sbase,
        const __nv_bfloat16* __restrict__ Ahi, const __nv_bfloat16* __restrict__ Alo,
        const __nv_bfloat16* __restrict__ Bhi, const __nv_bfloat16* __restrict__ Blo,
        int K, int m0, int n0, int kc, int tid) {
    size_t kb = (size_t)kc * 64;
    #pragma unroll
    for (int l = 0; l < 4; ++l) {
        int idx = tid + l * 256;
        int r = idx >> 3, cb = idx & 7;
        uint32_t doff = (r << 7) + ((cb ^ (r & 7)) << 4);
        const char* a_src  = (const char*)(Ahi + (size_t)(m0 + r) * K + kb) + cb * 16;
        const char* al_src = (const char*)(Alo + (size_t)(m0 + r) * K + kb) + cb * 16;
        const char* b_src  = (const char*)(Bhi + (size_t)(n0 + r) * K + kb) + cb * 16;
        const char* bl_src = (const char*)(Blo + (size_t)(n0 + r) * K + kb) + cb * 16;
        CP_ASYNC16(sbase + OFF_AHI + doff, a_src);
        CP_ASYNC16(sbase + OFF_ALO + doff, al_src);
        CP_ASYNC16(sbase + OFF_BHI + doff, b_src);
        CP_ASYNC16(sbase + OFF_BLO + doff, bl_src);
    }
}

template <int MODE>
__device__ __forceinline__ void gemm_core(
        const __nv_bfloat16* __restrict__ Ahi, const __nv_bfloat16* __restrict__ Alo,
        const __nv_bfloat16* __restrict__ Bhi, const __nv_bfloat16* __restrict__ Blo,
        int K, const float* __restrict__ bias, const float* __restrict__ res,
        float* __restrict__ outf,
        __nv_bfloat16* __restrict__ outhi, __nv_bfloat16* __restrict__ outlo,
        int m0, int n0, int ldc, char* abuf, int zkind) {
    extern __shared__ char dynsmem[];
    uint32_t sb = smem_u32(dynsmem);
    const int tid  = threadIdx.x;
    const int lane = tid & 31;
    const int wid  = tid >> 5;
    const int wm   = wid & 3;
    const int wn   = wid >> 2;

    const int a_r   = (lane & 7) + ((lane >> 3) & 1) * 8;
    const int a_cb0 = lane >> 4;
    const int b_r   = (lane & 7) + ((lane >> 4) << 3);
    const int b_cb0 = (lane >> 3) & 1;

    float acc[2][8][4];
    #pragma unroll
    for (int i = 0; i < 2; ++i)
        #pragma unroll
        for (int j = 0; j < 8; ++j)
            #pragma unroll
            for (int q = 0; q < 4; ++q) acc[i][j][q] = 0.f;

    const int nc = K >> 6;
    g2s_stage(sb, Ahi, Alo, Bhi, Blo, K, m0, n0, 0, tid);
    CP_COMMIT();

    for (int c = 0; c < nc; ++c) {
        if (c + 1 < nc) {
            g2s_stage(sb + ((c + 1) & 1) * STAGE_SZ, Ahi, Alo, Bhi, Blo, K, m0, n0, c + 1, tid);
            CP_COMMIT();
            CP_WAIT1();
        } else {
            CP_WAIT0();
        }
        __syncthreads();

        uint32_t stg = sb + (c & 1) * STAGE_SZ;
        #pragma unroll
        for (int ks = 0; ks < 4; ++ks) {
            uint32_t ah[2][4], al[2][4], bh[4][4], bl[4][4];
            #pragma unroll
            for (int mt = 0; mt < 2; ++mt) {
                int row = wm * 32 + mt * 16 + a_r;
                int cb  = ks * 2 + a_cb0;
                uint32_t off = (row << 7) + (((cb) ^ (row & 7)) << 4);
                ldsm_x4(stg + OFF_AHI + off, ah[mt]);
                ldsm_x4(stg + OFF_ALO + off, al[mt]);
            }
            #pragma unroll
            for (int bt = 0; bt < 4; ++bt) {
                int row = wn * 64 + bt * 16 + b_r;
                int cb  = ks * 2 + b_cb0;
                uint32_t off = (row << 7) + (((cb) ^ (row & 7)) << 4);
                ldsm_x4(stg + OFF_BHI + off, bh[bt]);
                ldsm_x4(stg + OFF_BLO + off, bl[bt]);
            }
            #pragma unroll
            for (int mt = 0; mt < 2; ++mt)
                #pragma unroll
                for (int nt = 0; nt < 8; ++nt) {
                    int bt = nt >> 1, hf = (nt & 1) * 2;
                    mma16816(acc[mt][nt], ah[mt], bh[bt][hf], bh[bt][hf + 1]);
                    mma16816(acc[mt][nt], ah[mt], bl[bt][hf], bl[bt][hf + 1]);
                    mma16816(acc[mt][nt], al[mt], bh[bt][hf], bh[bt][hf + 1]);
                }
        }
        __syncthreads();
    }

    const int gid = lane >> 2, tig = lane & 3;
    #pragma unroll
    for (int mt = 0; mt < 2; ++mt) {
        int m = m0 + wm * 32 + mt * 16 + gid;
        #pragma unroll
        for (int nt = 0; nt < 8; ++nt) {
            int n = n0 + wn * 64 + nt * 8 + tig * 2;
            float* a = acc[mt][nt];
            float b0 = bias[n], b1 = bias[n + 1];
            if (MODE == 1) {
                float v00 = fmaxf(a[0] + b0, 0.f), v01 = fmaxf(a[1] + b1, 0.f);
                float v10 = fmaxf(a[2] + b0, 0.f), v11 = fmaxf(a[3] + b1, 0.f);
                __nv_bfloat162 h0, l0, h1, l1;
                h0.x = __float2bfloat16(v00); h0.y = __float2bfloat16(v01);
                l0.x = __float2bfloat16(v00 - __bfloat162float(h0.x));
                l0.y = __float2bfloat16(v01 - __bfloat162float(h0.y));
                h1.x = __float2bfloat16(v10); h1.y = __float2bfloat16(v11);
                l1.x = __float2bfloat16(v10 - __bfloat162float(h1.x));
                l1.y = __float2bfloat16(v11 - __bfloat162float(h1.y));
                *(__nv_bfloat162*)(outhi + (size_t)m * ldc + n) = h0;
                *(__nv_bfloat162*)(outlo + (size_t)m * ldc + n) = l0;
                *(__nv_bfloat162*)(outhi + (size_t)(m + 8) * ldc + n) = h1;
                *(__nv_bfloat162*)(outlo + (size_t)(m + 8) * ldc + n) = l1;
            } else if (MODE == 2) {
                float2 r0 = *(const float2*)(res + (size_t)m * ldc + n);
                float2 r1 = *(const float2*)(res + (size_t)(m + 8) * ldc + n);
                float2 v0 = make_float2(a[0] + b0 + r0.x, a[1] + b1 + r0.y);
                float2 v1 = make_float2(a[2] + b0 + r1.x, a[3] + b1 + r1.y);
                *(float2*)(outf + (size_t)m * ldc + n) = v0;
                *(float2*)(outf + (size_t)(m + 8) * ldc + n) = v1;
            } else {   // MODE 3: attention-layout q/k/v
                float sc = (zkind == 0) ? QSCALE : 1.0f;
                float v00 = (a[0] + b0) * sc, v01 = (a[1] + b1) * sc;
                float v10 = (a[2] + b0) * sc, v11 = (a[3] + b1) * sc;
                int gI = m >> 8;
                int h  = n >> 5, d = n & 31;
                if (zkind < 2) {
                    char* base = abuf + ((size_t)(gI * 8 + h) * 256) * 128;
                    #pragma unroll
                    for (int rr = 0; rr < 2; ++rr) {
                        int r = (m & 255) + rr * 8;
                        float x0 = rr ? v10 : v00, x1 = rr ? v11 : v01;
                        __nv_bfloat16 hh0 = __float2bfloat16(x0);
                        __nv_bfloat16 hh1 = __float2bfloat16(x1);
                        uint32_t hi = pack_bf2(x0, x1);
                        uint32_t lo = pack_bf2(x0 - __bfloat162float(hh0),
                                               x1 - __bfloat162float(hh1));
                        int cb = d >> 3, bi = (2 * d) & 15;
                        *(uint32_t*)(base + r * 128 + (((cb)     ^ (r & 7)) << 4) + bi) = hi;
                        *(uint32_t*)(base + r * 128 + (((cb + 4) ^ (r & 7)) << 4) + bi) = lo;
                    }
                } else {
                    char* base = abuf + ((size_t)(gI * 8 + h) * 32) * 1024;
                    #pragma unroll
                    for (int rr = 0; rr < 2; ++rr) {
                        int t = (m & 255) + rr * 8;      // token (vT column)
                        float x0 = rr ? v10 : v00, x1 = rr ? v11 : v01;
                        int cb = t >> 3, bi = (2 * t) & 15;
                        #pragma unroll
                        for (int dd0 = 0; dd0 < 2; ++dd0) {
                            int dd = d + dd0;
                            float xv = dd0 ? x1 : x0;
                            __nv_bfloat16 hh = __float2bfloat16(xv);
                            __nv_bfloat16 ll = __float2bfloat16(xv - __bfloat162float(hh));
                            uint32_t off = dd * 1024 + ((cb ^ (dd & 7)) << 4) + bi;
                            *(__nv_bfloat16*)(base + off)       = hh;
                            *(__nv_bfloat16*)(base + off + 512) = ll;
                        }
                    }
                }
            }
        }
    }
}

__global__ __launch_bounds__(256, 1) void qkv_kernel(const float* bq, const float* bk, const float* bv) {
    const __nv_bfloat16 *Bh, *Bl;
    const float* bias;
    char* abuf;
    int zk = blockIdx.z;
    if (zk == 0)      { Bh = g_wqT_hi; Bl = g_wqT_lo; bias = bq; abuf = g_qa; }
    else if (zk == 1) { Bh = g_wkT_hi; Bl = g_wkT_lo; bias = bk; abuf = g_ka; }
    else              { Bh = g_wvT_hi; Bl = g_wvT_lo; bias = bv; abuf = g_va; }
    gemm_core<3>(g_xn_hi, g_xn_lo, Bh, Bl, 256, bias, nullptr,
                 nullptr, nullptr, nullptr, blockIdx.x * 128, blockIdx.y * 128, 256, abuf, zk);
}
__global__ __launch_bounds__(256, 1) void ff1_kernel(const float* bf1) {
    gemm_core<1>(g_h_hi, g_h_lo, g_wf1T_hi, g_wf1T_lo, 256, bf1, nullptr,
                 nullptr, g_ff1_hi, g_ff1_lo, blockIdx.x * 128, blockIdx.y * 128, 1024, nullptr, 0);
}
__global__ __launch_bounds__(256, 1) void ff2_kernel(const float* bf2, float* out) {
    gemm_core<2>(g_ff1_hi, g_ff1_lo, g_wf2T_hi, g_wf2T_lo, 1024, bf2, g_xout,
                 out, nullptr, nullptr, blockIdx.x * 128, blockIdx.y * 128, 256, nullptr, 0);
}

// ---------------------------------------------------------------------------
// Tensor-core attention: one CTA per (g,h), 8 warps.
// smem: k[256][128] | vT[32][1024] | q[256][128] | scores f32 [32][260] |
//       P [32][1024] (hi|lo) | partials 8x[32][32] f32
// ---------------------------------------------------------------------------
#define ASM_K 0
#define ASM_V 32768
#define ASM_Q 65536
#define ASM_S 98304
#define S_STRIDE_B 1040        // 260 floats
#define ASM_P (ASM_S + 32 * S_STRIDE_B)      // 131584
#define ASM_R (ASM_P + 32768)                 // 164352
#define ATTN_SMEM (ASM_R + 32768)             // 197120

__global__ __launch_bounds__(256, 1) void attn_kernel(
        const float* __restrict__ x, float* __restrict__ xout) {
    extern __shared__ char smc[];
    uint32_t sb = smem_u32(smc);
    int gh = blockIdx.x, g = gh >> 3, h = gh & 7;
    int tid = threadIdx.x, lane = tid & 31, wid = tid >> 5;

    // copy pre-swizzled tiles (32 KB each)
    {
        const char* ks = g_ka + (size_t)gh * 32768;
        const char* vs = g_va + (size_t)gh * 32768;
        const char* qs = g_qa + (size_t)gh * 32768;
        for (int i = tid; i < 2048; i += 256) {
            CP_ASYNC16(sb + ASM_K + i * 16, ks + i * 16);
            CP_ASYNC16(sb + ASM_V + i * 16, vs + i * 16);
            CP_ASYNC16(sb + ASM_Q + i * 16, qs + i * 16);
        }
        CP_COMMIT(); CP_WAIT0();
    }
    __syncthreads();

    const int a_r   = (lane & 7) + ((lane >> 3) & 1) * 8;
    const int a_cb0 = lane >> 4;
    const int b_r   = (lane & 7) + ((lane >> 4) << 3);
    const int b_cb0 = (lane >> 3) & 1;
    const int gid = lane >> 2, tig = lane & 3;

    for (int c = 0; c < 8; ++c) {
        int m0 = c * 32;
        // ---- QK^T: warp wid owns keys [wid*32, wid*32+32) ----
        {
            float acc[2][4][4];
            #pragma unroll
            for (int i = 0; i < 2; ++i)
                #pragma unroll
                for (int j = 0; j < 4; ++j)
                    #pragma unroll
                    for (int q = 0; q < 4; ++q) acc[i][j][q] = 0.f;
            #pragma unroll
            for (int ks = 0; ks < 2; ++ks) {
                uint32_t ah[2][4], al[2][4], kh[2][4], kl[2][4];
                #pragma unroll
                for (int mt = 0; mt < 2; ++mt) {
                    int row = m0 + mt * 16 + a_r;
                    int cb = ks * 2 + a_cb0;
                    uint32_t off = ASM_Q + row * 128 + (((cb)     ^ (row & 7)) << 4);
                    uint32_t ofl = ASM_Q + row * 128 + (((cb + 4) ^ (row & 7)) << 4);
                    ldsm_x4(sb + off, ah[mt]);
                    ldsm_x4(sb + ofl, al[mt]);
                }
                #pragma unroll
                for (int bt = 0; bt < 2; ++bt) {
                    int row = wid * 32 + bt * 16 + b_r;
                    int cb = ks * 2 + b_cb0;
                    uint32_t off = ASM_K + row * 128 + (((cb)     ^ (row & 7)) << 4);
                    uint32_t ofl = ASM_K + row * 128 + (((cb + 4) ^ (row & 7)) << 4);
                    ldsm_x4(sb + off, kh[bt]);
                    ldsm_x4(sb + ofl, kl[bt]);
                }
                #pragma unroll
                for (int mt = 0; mt < 2; ++mt)
                    #pragma unroll
                    for (int nt = 0; nt < 4; ++nt) {
                        int bt = nt >> 1, hf = (nt & 1) * 2;
                        mma16816(acc[mt][nt], ah[mt], kh[bt][hf], kh[bt][hf + 1]);
                        mma16816(acc[mt][nt], ah[mt], kl[bt][hf], kl[bt][hf + 1]);
                        mma16816(acc[mt][nt], al[mt], kh[bt][hf], kh[bt][hf + 1]);
                    }
            }
            #pragma unroll
            for (int mt = 0; mt < 2; ++mt)
                #pragma unroll
                for (int nt = 0; nt < 4; ++nt) {
                    int row = mt * 16 + gid;
                    int col = wid * 32 + nt * 8 + tig * 2;
                    *(float2*)(smc + ASM_S + row * S_STRIDE_B + col * 4) =
                        make_float2(acc[mt][nt][0], acc[mt][nt][1]);
                    *(float2*)(smc + ASM_S + (row + 8) * S_STRIDE_B + col * 4) =
                        make_float2(acc[mt][nt][2], acc[mt][nt][3]);
                }
        }
        __syncthreads();
        // ---- edge bias via capped adjacency ----
        #pragma unroll
        for (int rr = 0; rr < 4; ++rr) {
            int r = wid * 4 + rr;
            int node = g * 256 + m0 + r;
            int cnt = g_cnt[node];
            cnt = cnt < DEG_CAP ? cnt : DEG_CAP;
            for (int j = lane; j < cnt; j += 32) {
                uint32_t a = g_adj[node * DEG_CAP + j];
                int dst = a & 255;
                int eid = a >> 8;
                atomicAdd((float*)(smc + ASM_S + r * S_STRIDE_B + dst * 4),
                          g_ew[eid * 8 + h]);
            }
        }
        __syncthreads();
        // ---- softmax + P -> bf16 hi/lo (swizzled) ----
        #pragma unroll
        for (int rr = 0; rr < 4; ++rr) {
            int r = wid * 4 + rr;
            const float* srow = (const float*)(smc + ASM_S + r * S_STRIDE_B);
            float vals[8];
            float mx = -1e30f;
            #pragma unroll
            for (int i = 0; i < 8; ++i) {
                vals[i] = srow[lane + 32 * i];
                mx = fmaxf(mx, vals[i]);
            }
            mx = warp_max(mx);
            float sum = 0.f;
            #pragma unroll
            for (int i = 0; i < 8; ++i) { vals[i] = __expf(vals[i] - mx); sum += vals[i]; }
            sum = warp_sum(sum);
            float inv = __frcp_rn(sum);
            #pragma unroll
            for (int i = 0; i < 8; ++i) {
                float p = vals[i] * inv;
                int t = lane + 32 * i;
                __nv_bfloat16 ph = __float2bfloat16(p);
                __nv_bfloat16 pl = __float2bfloat16(p - __bfloat162float(ph));
                int cb = t >> 3;
                uint32_t off = ASM_P + r * 1024 + ((cb ^ (r & 7)) << 4) + ((2 * t) & 15);
                *(__nv_bfloat16*)(smc + off)       = ph;
                *(__nv_bfloat16*)(smc + off + 512) = pl;
            }
        }
        __syncthreads();
        // ---- P @ V: split-K, warp wid owns ksteps [wid*2, wid*2+2) ----
        {
            float acc[2][4][4];
            #pragma unroll
            for (int i = 0; i < 2; ++i)
                #pragma unroll
                for (int j = 0; j < 4; ++j)
                    #pragma unroll
                    for (int q = 0; q < 4; ++q) acc[i][j][q] = 0.f;
            #pragma unroll
            for (int kk = 0; kk < 2; ++kk) {
                int ks = wid * 2 + kk;
                uint32_t ph[2][4], pl[2][4], vh[2][4], vl[2][4];
                #pragma unroll
                for (int mt = 0; mt < 2; ++mt) {
                    int row = mt * 16 + a_r;
                    int cb = ks * 2 + a_cb0;
                    uint32_t off = ASM_P + row * 1024 + ((cb ^ (row & 7)) << 4);
                    ldsm_x4(sb + off, ph[mt]);
                    ldsm_x4(sb + off + 512, pl[mt]);
                }
                #pragma unroll
                for (int bt = 0; bt < 2; ++bt) {
                    int row = bt * 16 + b_r;
                    int cb = ks * 2 + b_cb0;
                    uint32_t off = ASM_V + row * 1024 + ((cb ^ (row & 7)) << 4);
                    ldsm_x4(sb + off, vh[bt]);
                    ldsm_x4(sb + off + 512, vl[bt]);
                }
                #pragma unroll
                for (int mt = 0; mt < 2; ++mt)
                    #pragma unroll
                    for (int nt = 0; nt < 4; ++nt) {
                        int bt = nt >> 1, hf = (nt & 1) * 2;
                        mma16816(acc[mt][nt], ph[mt], vh[bt][hf], vh[bt][hf + 1]);
                        mma16816(acc[mt][nt], ph[mt], vl[bt][hf], vl[bt][hf + 1]);
                        mma16816(acc[mt][nt], pl[mt], vh[bt][hf], vh[bt][hf + 1]);
                    }
            }
            #pragma unroll
            for (int mt = 0; mt < 2; ++mt)
                #pragma unroll
                for (int nt = 0; nt < 4; ++nt) {
                    int row = mt * 16 + gid;
                    int col = nt * 8 + tig * 2;
                    *(float2*)(smc + ASM_R + wid * 4096 + row * 128 + col * 4) =
                        make_float2(acc[mt][nt][0], acc[mt][nt][1]);
                    *(float2*)(smc + ASM_R + wid * 4096 + (row + 8) * 128 + col * 4) =
                        make_float2(acc[mt][nt][2], acc[mt][nt][3]);
                }
        }
        __syncthreads();
        // ---- reduce 8 partials + residual + write ----
        {
            int row = tid >> 3, colb = (tid & 7) * 4;
            float4 s4 = make_float4(0.f, 0.f, 0.f, 0.f);
            #pragma unroll
            for (int w = 0; w < 8; ++w) {
                float4 t4 = *(const float4*)(smc + ASM_R + w * 4096 + row * 128 + colb * 4);
                s4.x += t4.x; s4.y += t4.y; s4.z += t4.z; s4.w += t4.w;
            }
            int gr = g * 256 + m0 + row;
            int col = h * 32 + colb;
            float4 xin = *(const float4*)(x + (size_t)gr * 256 + col);
            s4.x += xin.x; s4.y += xin.y; s4.z += xin.z; s4.w += xin.w;
            *(float4*)(xout + (size_t)gr * 256 + col) = s4;
        }
        __syncthreads();
    }
}

// ---------------------------------------------------------------------------
// Launch
// ---------------------------------------------------------------------------
extern "C" void kernel_launch(void* const* d_in, const int* in_sizes, int n_in,
                              void* d_out, int out_size) {
    const float* x    = (const float*)d_in[0];
    const void*  ei   =                d_in[1];
    const float* ea   = (const float*)d_in[2];
    const float* ln1w = (const float*)d_in[4];
    const float* ln1b = (const float*)d_in[5];
    const float* Wq   = (const float*)d_in[6];
    const float* bq   = (const float*)d_in[7];
    const float* Wk   = (const float*)d_in[8];
    const float* bk   = (const float*)d_in[9];
    const float* Wv   = (const float*)d_in[10];
    const float* bv   = (const float*)d_in[11];
    const float* We   = (const float*)d_in[12];
    const float* be   = (const float*)d_in[13];
    const float* ln2w = (const float*)d_in[14];
    const float* ln2b = (const float*)d_in[15];
    const float* Wf1  = (const float*)d_in[16];
    const float* bf1  = (const float*)d_in[17];
    const float* Wf2  = (const float*)d_in[18];
    const float* bf2  = (const float*)d_in[19];
    float* out = (float*)d_out;

    float *p_xout;
    __nv_bfloat16 *p_xnh, *p_xnl, *p_hh, *p_hl;
    cudaGetSymbolAddress((void**)&p_xout, g_xout);
    cudaGetSymbolAddress((void**)&p_xnh,  g_xn_hi);
    cudaGetSymbolAddress((void**)&p_xnl,  g_xn_lo);
    cudaGetSymbolAddress((void**)&p_hh,   g_h_hi);
    cudaGetSymbolAddress((void**)&p_hl,   g_h_lo);

    cudaFuncSetAttribute(attn_kernel, cudaFuncAttributeMaxDynamicSharedMemorySize, ATTN_SMEM);
    cudaFuncSetAttribute(qkv_kernel,  cudaFuncAttributeMaxDynamicSharedMemorySize, GEMM_SMEM);
    cudaFuncSetAttribute(ff1_kernel,  cudaFuncAttributeMaxDynamicSharedMemorySize, GEMM_SMEM);
    cudaFuncSetAttribute(ff2_kernel,  cudaFuncAttributeMaxDynamicSharedMemorySize, GEMM_SMEM);

    // prep (2 launches) + weight prep (1)
    detect_zero_kernel<<<GN_ / 256, 256>>>(ei);
    scatter_ew_kernel<<<E_ / 256, 256>>>(ei, ea, We, be);
    wprep_all_kernel<<<704, dim3(32, 8)>>>(Wq, Wk, Wv, Wf1, Wf2);

    // LN1 + QKV (writes attention-layout q/k/vT)
    ln_split_kernel<<<GN_ / 8, 256>>>(x, ln1w, ln1b, p_xnh, p_xnl);
    qkv_kernel<<<dim3(GN_ / 128, OUT_ / 128, 3), 256, GEMM_SMEM>>>(bq, bk, bv);

    // tensor-core attention (+ residual)
    attn_kernel<<<G_ * H_, 256, ATTN_SMEM>>>(x, p_xout);

    // LN2 + FFN
    ln_split_kernel<<<GN_ / 8, 256>>>(p_xout, ln2w, ln2b, p_hh, p_hl);
    ff1_kernel<<<dim3(GN_ / 128, FF_ / 128), 256, GEMM_SMEM>>>(bf1);
    ff2_kernel<<<dim3(GN_ / 128, OUT_ / 128), 256, GEMM_SMEM>>>(bf2, out);
}

// round 7
// speedup vs baseline: 2.0538x; 1.0142x over previous
#include <cuda_runtime.h>
#include <cuda_bf16.h>
#include <cstdint>
#include <math.h>

// ---------------------------------------------------------------------------
// Problem constants
// ---------------------------------------------------------------------------
#define G_   64
#define N_   256
#define GN_  (G_ * N_)        // 16384 nodes
#define H_   8
#define D_   32
#define IN_  256
#define OUT_ 256
#define FF_  1024
#define E_   (GN_ * 16)       // 262144 edges
#define EPS_ 1e-5f
#define QSCALE 0.17677669529663687f   // 1/sqrt(32)
#define DEG_CAP 64

// ---------------------------------------------------------------------------
// PTX helpers (sm_100 baseline: mma.sync + ldmatrix + cp.async)
// ---------------------------------------------------------------------------
__device__ __forceinline__ uint32_t smem_u32(const void* p) {
    uint32_t a;
    asm("{ .reg .u64 t; cvta.to.shared.u64 t, %1; cvt.u32.u64 %0, t; }" : "=r"(a) : "l"(p));
    return a;
}
#define CP_ASYNC16(dst, src) \
    asm volatile("cp.async.cg.shared.global [%0], [%1], 16;" :: "r"(dst), "l"(src))
#define CP_COMMIT() asm volatile("cp.async.commit_group;" ::: "memory")
#define CP_WAIT1()  asm volatile("cp.async.wait_group 1;" ::: "memory")
#define CP_WAIT0()  asm volatile("cp.async.wait_group 0;" ::: "memory")

__device__ __forceinline__ void ldsm_x4(uint32_t addr, uint32_t* r) {
    asm volatile("ldmatrix.sync.aligned.m8n8.x4.shared.b16 {%0,%1,%2,%3}, [%4];"
                 : "=r"(r[0]), "=r"(r[1]), "=r"(r[2]), "=r"(r[3]) : "r"(addr));
}
__device__ __forceinline__ void ldsm_x4_trans(uint32_t addr, uint32_t* r) {
    asm volatile("ldmatrix.sync.aligned.m8n8.x4.trans.shared.b16 {%0,%1,%2,%3}, [%4];"
                 : "=r"(r[0]), "=r"(r[1]), "=r"(r[2]), "=r"(r[3]) : "r"(addr));
}
__device__ __forceinline__ void mma16816(float* d, const uint32_t* a,
                                         uint32_t b0, uint32_t b1) {
    asm volatile(
        "mma.sync.aligned.m16n8k16.row.col.f32.bf16.bf16.f32 "
        "{%0,%1,%2,%3}, {%4,%5,%6,%7}, {%8,%9}, {%0,%1,%2,%3};"
        : "+f"(d[0]), "+f"(d[1]), "+f"(d[2]), "+f"(d[3])
        : "r"(a[0]), "r"(a[1]), "r"(a[2]), "r"(a[3]), "r"(b0), "r"(b1));
}
__device__ __forceinline__ uint32_t pack_bf2(float a, float b) {
    __nv_bfloat162 t;
    t.x = __float2bfloat16(a);
    t.y = __float2bfloat16(b);
    return *(uint32_t*)&t;
}

// ---------------------------------------------------------------------------
// Device scratch
// ---------------------------------------------------------------------------
__device__ __nv_bfloat16 g_xn_hi [GN_ * IN_],  g_xn_lo [GN_ * IN_];
__device__ __nv_bfloat16 g_h_hi  [GN_ * OUT_], g_h_lo  [GN_ * OUT_];
__device__ __nv_bfloat16 g_ff1_hi[GN_ * FF_],  g_ff1_lo[GN_ * FF_];
__device__ __nv_bfloat16 g_wqT_hi [OUT_ * IN_], g_wqT_lo [OUT_ * IN_];
__device__ __nv_bfloat16 g_wkT_hi [OUT_ * IN_], g_wkT_lo [OUT_ * IN_];
__device__ __nv_bfloat16 g_wvT_hi [OUT_ * IN_], g_wvT_lo [OUT_ * IN_];
__device__ __nv_bfloat16 g_wf1T_hi[FF_ * OUT_], g_wf1T_lo[FF_ * OUT_];
__device__ __nv_bfloat16 g_wf2T_hi[OUT_ * FF_], g_wf2T_lo[OUT_ * FF_];

// attention-ready buffers (pre-swizzled smem images, written by QKV epilogue)
// q/k/v: per (g,h): 256 token rows x 128B (hi d0..31 | lo d0..31), xor swizzle
__device__ __align__(128) char g_qa[512 * 32768];
__device__ __align__(128) char g_ka[512 * 32768];
__device__ __align__(128) char g_va[512 * 32768];

__device__ float g_ew  [E_ * H_];
__device__ float g_xout[GN_ * OUT_];

__device__ int      g_cnt[GN_];
__device__ uint32_t g_adj[GN_ * DEG_CAP];   // (eid << 8) | local_dst
__device__ int      g_is64;

// ---------------------------------------------------------------------------
// small helpers
// ---------------------------------------------------------------------------
__device__ __forceinline__ long long load_idx(const void* p, int i) {
    if (g_is64) return ((const long long*)p)[i];
    return (long long)(((const int*)p)[i]);
}
__device__ __forceinline__ float warp_sum(float v) {
    #pragma unroll
    for (int o = 16; o > 0; o >>= 1) v += __shfl_xor_sync(0xffffffffu, v, o);
    return v;
}
__device__ __forceinline__ float warp_max(float v) {
    #pragma unroll
    for (int o = 16; o > 0; o >>= 1) v = fmaxf(v, __shfl_xor_sync(0xffffffffu, v, o));
    return v;
}

// ---------------------------------------------------------------------------
// prep: dtype detect + zero counters (1 kernel), scatter + edge weights (1)
// ---------------------------------------------------------------------------
__global__ void detect_zero_kernel(const void* __restrict__ ei) {
    int i = blockIdx.x * 256 + threadIdx.x;
    g_cnt[i] = 0;
    if (blockIdx.x == 0) {
        __shared__ int bad;
        if (threadIdx.x == 0) bad = 0;
        __syncthreads();
        const long long* p = (const long long*)ei;
        long long v0 = p[threadIdx.x];
        long long v1 = p[256 + threadIdx.x];
        if (v0 < 0 || v0 >= GN_ || v1 < 0 || v1 >= GN_) atomicOr(&bad, 1);
        __syncthreads();
        if (threadIdx.x == 0) g_is64 = !bad;
    }
}
__global__ void scatter_ew_kernel(const void* __restrict__ ei,
                                  const float* __restrict__ ea,
                                  const float* __restrict__ We,
                                  const float* __restrict__ be) {
    int e = blockIdx.x * 256 + threadIdx.x;
    int src = (int)load_idx(ei, e);
    int dst = (int)load_idx(ei, E_ + e);
    int slot = atomicAdd(&g_cnt[src], 1);
    if (slot < DEG_CAP)
        g_adj[src * DEG_CAP + slot] = ((uint32_t)e << 8) | (uint32_t)(dst & (N_ - 1));
    float a0 = ea[2 * e], a1 = ea[2 * e + 1];
    #pragma unroll
    for (int h = 0; h < H_; ++h)
        g_ew[e * H_ + h] = a0 * We[h] + a1 * We[H_ + h] + be[h];
}

// ---------------------------------------------------------------------------
// Weight prep: all 5 matrices in one launch.  W[K,N] fp32 -> WT[N,K] hi/lo.
// ---------------------------------------------------------------------------
__global__ void wprep_all_kernel(const float* Wq, const float* Wk, const float* Wv,
                                 const float* Wf1, const float* Wf2) {
    __shared__ float t[32][33];
    int b = blockIdx.x;
    const float* W;
    __nv_bfloat16 *Th, *Tl;
    int K, Nn, tI;
    if (b < 64)       { W = Wq;  Th = g_wqT_hi;  Tl = g_wqT_lo;  K = IN_;  Nn = OUT_; tI = b; }
    else if (b < 128) { W = Wk;  Th = g_wkT_hi;  Tl = g_wkT_lo;  K = IN_;  Nn = OUT_; tI = b - 64; }
    else if (b < 192) { W = Wv;  Th = g_wvT_hi;  Tl = g_wvT_lo;  K = IN_;  Nn = OUT_; tI = b - 128; }
    else if (b < 448) { W = Wf1; Th = g_wf1T_hi; Tl = g_wf1T_lo; K = OUT_; Nn = FF_;  tI = b - 192; }
    else              { W = Wf2; Th = g_wf2T_hi; Tl = g_wf2T_lo; K = FF_;  Nn = OUT_; tI = b - 448; }
    int kt = K / 32;
    int k0 = (tI % kt) * 32, n0 = (tI / kt) * 32;
    int tx = threadIdx.x, ty = threadIdx.y;
    for (int i = ty; i < 32; i += 8)
        t[i][tx] = W[(size_t)(k0 + i) * Nn + n0 + tx];
    __syncthreads();
    for (int i = ty; i < 32; i += 8) {
        float v = t[tx][i];
        __nv_bfloat16 h = __float2bfloat16(v);
        size_t o = (size_t)(n0 + i) * K + k0 + tx;
        Th[o] = h;
        Tl[o] = __float2bfloat16(v - __bfloat162float(h));
    }
}

// ---------------------------------------------------------------------------
// LayerNorm -> bf16 hi/lo split output
// ---------------------------------------------------------------------------
__global__ __launch_bounds__(256) void ln_split_kernel(
        const float* __restrict__ x, const float* __restrict__ w,
        const float* __restrict__ b,
        __nv_bfloat16* __restrict__ ohi, __nv_bfloat16* __restrict__ olo) {
    int row  = blockIdx.x * 8 + (threadIdx.x >> 5);
    int lane = threadIdx.x & 31;
    const float* xr = x + (size_t)row * 256;
    float v[8];
    float s = 0.f;
    #pragma unroll
    for (int i = 0; i < 8; ++i) { v[i] = xr[lane + 32 * i]; s += v[i]; }
    s = warp_sum(s);
    float mean = s * (1.f / 256.f);
    float sq = 0.f;
    #pragma unroll
    for (int i = 0; i < 8; ++i) { float d = v[i] - mean; sq += d * d; }
    sq = warp_sum(sq);
    float rstd = rsqrtf(sq * (1.f / 256.f) + EPS_);
    #pragma unroll
    for (int i = 0; i < 8; ++i) {
        int c = lane + 32 * i;
        float y = (v[i] - mean) * rstd * w[c] + b[c];
        __nv_bfloat16 h = __float2bfloat16(y);
        ohi[(size_t)row * 256 + c] = h;
        olo[(size_t)row * 256 + c] = __float2bfloat16(y - __bfloat162float(h));
    }
}

// ---------------------------------------------------------------------------
// mma.sync GEMM core.  C tile 128x128, split-bf16 (3 products).
// 512 threads, 16 warps (4x4), warp tile 32x32: 4 warps/SMSP for latency
// hiding.  3-stage cp.async pipeline, ONE __syncthreads per K64 chunk.
// MODE 1: relu+bias -> bf16 hi/lo; MODE 2: fp32+bias+residual;
// MODE 3: qkv -> attention-layout buffers (q scaled; q/k/v identical layout).
// ---------------------------------------------------------------------------
#define STAGES   3
#define STAGE_SZ 65536
#define OFF_AHI  0
#define OFF_ALO  16384
#define OFF_BHI  32768
#define OFF_BLO  49152
#define GEMM_SMEM (STAGES * STAGE_SZ)   // 196608

__device__ __forceinline__ void g2s_stage(uint32_t sbase,
        const __nv_bfloat16* __restrict__ Ahi, const __nv_bfloat16* __restrict__ Alo,
        const __nv_bfloat16* __restrict__ Bhi, const __nv_bfloat16* __restrict__ Blo,
        int K, int m0, int n0, int kc, int tid) {
    size_t kb = (size_t)kc * 64;
    #pragma unroll
    for (int l = 0; l < 2; ++l) {
        int idx = tid + l * 512;          // 1024 chunks: r = idx/8, cb = idx%8
        int r = idx >> 3, cb = idx & 7;
        uint32_t doff = (r << 7) + ((cb ^ (r & 7)) << 4);
        const char* a_src  = (const char*)(Ahi + (size_t)(m0 + r) * K + kb) + cb * 16;
        const char* al_src = (const char*)(Alo + (size_t)(m0 + r) * K + kb) + cb * 16;
        const char* b_src  = (const char*)(Bhi + (size_t)(n0 + r) * K + kb) + cb * 16;
        const char* bl_src = (const char*)(Blo + (size_t)(n0 + r) * K + kb) + cb * 16;
        CP_ASYNC16(sbase + OFF_AHI + doff, a_src);
        CP_ASYNC16(sbase + OFF_ALO + doff, al_src);
        CP_ASYNC16(sbase + OFF_BHI + doff, b_src);
        CP_ASYNC16(sbase + OFF_BLO + doff, bl_src);
    }
}

template <int MODE>
__device__ __forceinline__ void gemm_core(
        const __nv_bfloat16* __restrict__ Ahi, const __nv_bfloat16* __restrict__ Alo,
        const __nv_bfloat16* __restrict__ Bhi, const __nv_bfloat16* __restrict__ Blo,
        int K, const float* __restrict__ bias, const float* __restrict__ res,
        float* __restrict__ outf,
        __nv_bfloat16* __restrict__ outhi, __nv_bfloat16* __restrict__ outlo,
        int m0, int n0, int ldc, char* abuf, int zkind) {
    extern __shared__ char dynsmem[];
    uint32_t sb = smem_u32(dynsmem);
    const int tid  = threadIdx.x;
    const int lane = tid & 31;
    const int wid  = tid >> 5;
    const int wm   = wid & 3;             // 4 warps in M -> 32*wm
    const int wn   = wid >> 2;            // 4 warps in N -> 32*wn

    const int a_r   = (lane & 7) + ((lane >> 3) & 1) * 8;
    const int a_cb0 = lane >> 4;
    const int b_r   = (lane & 7) + ((lane >> 4) << 3);
    const int b_cb0 = (lane >> 3) & 1;

    float acc[2][4][4];
    #pragma unroll
    for (int i = 0; i < 2; ++i)
        #pragma unroll
        for (int j = 0; j < 4; ++j)
            #pragma unroll
            for (int q = 0; q < 4; ++q) acc[i][j][q] = 0.f;

    const int nc = K >> 6;
    g2s_stage(sb, Ahi, Alo, Bhi, Blo, K, m0, n0, 0, tid);
    CP_COMMIT();
    if (nc > 1) {
        g2s_stage(sb + STAGE_SZ, Ahi, Alo, Bhi, Blo, K, m0, n0, 1, tid);
        CP_COMMIT();
    }

    for (int c = 0; c < nc; ++c) {
        if (c == nc - 1) CP_WAIT0(); else CP_WAIT1();
        __syncthreads();
        if (c + 2 < nc) {
            g2s_stage(sb + ((c + 2) % 3) * STAGE_SZ, Ahi, Alo, Bhi, Blo, K, m0, n0, c + 2, tid);
            CP_COMMIT();
        }
        uint32_t stg = sb + (c % 3) * STAGE_SZ;
        #pragma unroll
        for (int ks = 0; ks < 4; ++ks) {
            uint32_t ah[2][4], al[2][4], bh[2][4], bl[2][4];
            #pragma unroll
            for (int mt = 0; mt < 2; ++mt) {
                int row = wm * 32 + mt * 16 + a_r;
                int cb  = ks * 2 + a_cb0;
                uint32_t off = (row << 7) + ((cb ^ (row & 7)) << 4);
                ldsm_x4(stg + OFF_AHI + off, ah[mt]);
                ldsm_x4(stg + OFF_ALO + off, al[mt]);
            }
            #pragma unroll
            for (int bt = 0; bt < 2; ++bt) {
                int row = wn * 32 + bt * 16 + b_r;
                int cb  = ks * 2 + b_cb0;
                uint32_t off = (row << 7) + ((cb ^ (row & 7)) << 4);
                ldsm_x4(stg + OFF_BHI + off, bh[bt]);
                ldsm_x4(stg + OFF_BLO + off, bl[bt]);
            }
            #pragma unroll
            for (int mt = 0; mt < 2; ++mt)
                #pragma unroll
                for (int nt = 0; nt < 4; ++nt) {
                    int bt = nt >> 1, hf = (nt & 1) * 2;
                    mma16816(acc[mt][nt], ah[mt], bh[bt][hf], bh[bt][hf + 1]);
                    mma16816(acc[mt][nt], ah[mt], bl[bt][hf], bl[bt][hf + 1]);
                    mma16816(acc[mt][nt], al[mt], bh[bt][hf], bh[bt][hf + 1]);
                }
        }
    }

    const int gid = lane >> 2, tig = lane & 3;
    #pragma unroll
    for (int mt = 0; mt < 2; ++mt) {
        int m = m0 + wm * 32 + mt * 16 + gid;
        #pragma unroll
        for (int nt = 0; nt < 4; ++nt) {
            int n = n0 + wn * 32 + nt * 8 + tig * 2;
            float* a = acc[mt][nt];
            float b0 = bias[n], b1 = bias[n + 1];
            if (MODE == 1) {
                float v00 = fmaxf(a[0] + b0, 0.f), v01 = fmaxf(a[1] + b1, 0.f);
                float v10 = fmaxf(a[2] + b0, 0.f), v11 = fmaxf(a[3] + b1, 0.f);
                __nv_bfloat162 h0, l0, h1, l1;
                h0.x = __float2bfloat16(v00); h0.y = __float2bfloat16(v01);
                l0.x = __float2bfloat16(v00 - __bfloat162float(h0.x));
                l0.y = __float2bfloat16(v01 - __bfloat162float(h0.y));
                h1.x = __float2bfloat16(v10); h1.y = __float2bfloat16(v11);
                l1.x = __float2bfloat16(v10 - __bfloat162float(h1.x));
                l1.y = __float2bfloat16(v11 - __bfloat162float(h1.y));
                *(__nv_bfloat162*)(outhi + (size_t)m * ldc + n) = h0;
                *(__nv_bfloat162*)(outlo + (size_t)m * ldc + n) = l0;
                *(__nv_bfloat162*)(outhi + (size_t)(m + 8) * ldc + n) = h1;
                *(__nv_bfloat162*)(outlo + (size_t)(m + 8) * ldc + n) = l1;
            } else if (MODE == 2) {
                float2 r0 = *(const float2*)(res + (size_t)m * ldc + n);
                float2 r1 = *(const float2*)(res + (size_t)(m + 8) * ldc + n);
                float2 v0 = make_float2(a[0] + b0 + r0.x, a[1] + b1 + r0.y);
                float2 v1 = make_float2(a[2] + b0 + r1.x, a[3] + b1 + r1.y);
                *(float2*)(outf + (size_t)m * ldc + n) = v0;
                *(float2*)(outf + (size_t)(m + 8) * ldc + n) = v1;
            } else {   // MODE 3: attention-layout q/k/v (identical layout now)
                float sc = (zkind == 0) ? QSCALE : 1.0f;
                float v00 = (a[0] + b0) * sc, v01 = (a[1] + b1) * sc;
                float v10 = (a[2] + b0) * sc, v11 = (a[3] + b1) * sc;
                int gI = m >> 8;
                int h  = n >> 5, d = n & 31;
                char* base = abuf + ((size_t)(gI * 8 + h) * 256) * 128;
                int cb = d >> 3, bi = (2 * d) & 15;
                #pragma unroll
                for (int rr = 0; rr < 2; ++rr) {
                    int r = (m & 255) + rr * 8;
                    float x0 = rr ? v10 : v00, x1 = rr ? v11 : v01;
                    __nv_bfloat16 hh0 = __float2bfloat16(x0);
                    __nv_bfloat16 hh1 = __float2bfloat16(x1);
                    uint32_t hi = pack_bf2(x0, x1);
                    uint32_t lo = pack_bf2(x0 - __bfloat162float(hh0),
                                           x1 - __bfloat162float(hh1));
                    *(uint32_t*)(base + r * 128 + (((cb)     ^ (r & 7)) << 4) + bi) = hi;
                    *(uint32_t*)(base + r * 128 + (((cb + 4) ^ (r & 7)) << 4) + bi) = lo;
                }
            }
        }
    }
}

__global__ __launch_bounds__(512, 1) void qkv_kernel(const float* bq, const float* bk, const float* bv) {
    const __nv_bfloat16 *Bh, *Bl;
    const float* bias;
    char* abuf;
    int zk = blockIdx.z;
    if (zk == 0)      { Bh = g_wqT_hi; Bl = g_wqT_lo; bias = bq; abuf = g_qa; }
    else if (zk == 1) { Bh = g_wkT_hi; Bl = g_wkT_lo; bias = bk; abuf = g_ka; }
    else              { Bh = g_wvT_hi; Bl = g_wvT_lo; bias = bv; abuf = g_va; }
    gemm_core<3>(g_xn_hi, g_xn_lo, Bh, Bl, 256, bias, nullptr,
                 nullptr, nullptr, nullptr, blockIdx.x * 128, blockIdx.y * 128, 256, abuf, zk);
}
__global__ __launch_bounds__(512, 1) void ff1_kernel(const float* bf1) {
    gemm_core<1>(g_h_hi, g_h_lo, g_wf1T_hi, g_wf1T_lo, 256, bf1, nullptr,
                 nullptr, g_ff1_hi, g_ff1_lo, blockIdx.x * 128, blockIdx.y * 128, 1024, nullptr, 0);
}
__global__ __launch_bounds__(512, 1) void ff2_kernel(const float* bf2, float* out) {
    gemm_core<2>(g_ff1_hi, g_ff1_lo, g_wf2T_hi, g_wf2T_lo, 1024, bf2, g_xout,
                 out, nullptr, nullptr, blockIdx.x * 128, blockIdx.y * 128, 256, nullptr, 0);
}

// ---------------------------------------------------------------------------
// Tensor-core attention: one CTA per (g,h), 8 warps.  V now token-major
// (same layout as K); P@V uses ldmatrix.trans for the B operand.
// ---------------------------------------------------------------------------
#define ASM_K 0
#define ASM_V 32768
#define ASM_Q 65536
#define ASM_S 98304
#define S_STRIDE_B 1040        // 260 floats
#define ASM_P (ASM_S + 32 * S_STRIDE_B)      // 131584
#define ASM_R (ASM_P + 32768)                 // 164352
#define ATTN_SMEM (ASM_R + 32768)             // 197120

__global__ __launch_bounds__(256, 1) void attn_kernel(
        const float* __restrict__ x, float* __restrict__ xout) {
    extern __shared__ char smc[];
    uint32_t sb = smem_u32(smc);
    int gh = blockIdx.x, g = gh >> 3, h = gh & 7;
    int tid = threadIdx.x, lane = tid & 31, wid = tid >> 5;

    {
        const char* ks = g_ka + (size_t)gh * 32768;
        const char* vs = g_va + (size_t)gh * 32768;
        const char* qs = g_qa + (size_t)gh * 32768;
        for (int i = tid; i < 2048; i += 256) {
            CP_ASYNC16(sb + ASM_K + i * 16, ks + i * 16);
            CP_ASYNC16(sb + ASM_V + i * 16, vs + i * 16);
            CP_ASYNC16(sb + ASM_Q + i * 16, qs + i * 16);
        }
        CP_COMMIT(); CP_WAIT0();
    }
    __syncthreads();

    const int a_r   = (lane & 7) + ((lane >> 3) & 1) * 8;
    const int a_cb0 = lane >> 4;
    const int b_r   = (lane & 7) + ((lane >> 4) << 3);
    const int b_cb0 = (lane >> 3) & 1;
    const int gid = lane >> 2, tig = lane & 3;
    // trans-load lane decomposition for P@V (rows = tokens = k)
    const int t_r   = (lane & 7) + ((lane >> 3) & 1) * 8;  // token within k16
    const int t_dc  = lane >> 4;                           // d 8-block within n16

    for (int c = 0; c < 8; ++c) {
        int m0 = c * 32;
        // ---- QK^T: warp wid owns keys [wid*32, wid*32+32) ----
        {
            float acc[2][4][4];
            #pragma unroll
            for (int i = 0; i < 2; ++i)
                #pragma unroll
                for (int j = 0; j < 4; ++j)
                    #pragma unroll
                    for (int q = 0; q < 4; ++q) acc[i][j][q] = 0.f;
            #pragma unroll
            for (int ks = 0; ks < 2; ++ks) {
                uint32_t ah[2][4], al[2][4], kh[2][4], kl[2][4];
                #pragma unroll
                for (int mt = 0; mt < 2; ++mt) {
                    int row = m0 + mt * 16 + a_r;
                    int cb = ks * 2 + a_cb0;
                    uint32_t off = ASM_Q + row * 128 + (((cb)     ^ (row & 7)) << 4);
                    uint32_t ofl = ASM_Q + row * 128 + (((cb + 4) ^ (row & 7)) << 4);
                    ldsm_x4(sb + off, ah[mt]);
                    ldsm_x4(sb + ofl, al[mt]);
                }
                #pragma unroll
                for (int bt = 0; bt < 2; ++bt) {
                    int row = wid * 32 + bt * 16 + b_r;
                    int cb = ks * 2 + b_cb0;
                    uint32_t off = ASM_K + row * 128 + (((cb)     ^ (row & 7)) << 4);
                    uint32_t ofl = ASM_K + row * 128 + (((cb + 4) ^ (row & 7)) << 4);
                    ldsm_x4(sb + off, kh[bt]);
                    ldsm_x4(sb + ofl, kl[bt]);
                }
                #pragma unroll
                for (int mt = 0; mt < 2; ++mt)
                    #pragma unroll
                    for (int nt = 0; nt < 4; ++nt) {
                        int bt = nt >> 1, hf = (nt & 1) * 2;
                        mma16816(acc[mt][nt], ah[mt], kh[bt][hf], kh[bt][hf + 1]);
                        mma16816(acc[mt][nt], ah[mt], kl[bt][hf], kl[bt][hf + 1]);
                        mma16816(acc[mt][nt], al[mt], kh[bt][hf], kh[bt][hf + 1]);
                    }
            }
            #pragma unroll
            for (int mt = 0; mt < 2; ++mt)
                #pragma unroll
                for (int nt = 0; nt < 4; ++nt) {
                    int row = mt * 16 + gid;
                    int col = wid * 32 + nt * 8 + tig * 2;
                    *(float2*)(smc + ASM_S + row * S_STRIDE_B + col * 4) =
                        make_float2(acc[mt][nt][0], acc[mt][nt][1]);
                    *(float2*)(smc + ASM_S + (row + 8) * S_STRIDE_B + col * 4) =
                        make_float2(acc[mt][nt][2], acc[mt][nt][3]);
                }
        }
        __syncthreads();
        // ---- edge bias via capped adjacency ----
        #pragma unroll
        for (int rr = 0; rr < 4; ++rr) {
            int r = wid * 4 + rr;
            int node = g * 256 + m0 + r;
            int cnt = g_cnt[node];
            cnt = cnt < DEG_CAP ? cnt : DEG_CAP;
            for (int j = lane; j < cnt; j += 32) {
                uint32_t a = g_adj[node * DEG_CAP + j];
                int dst = a & 255;
                int eid = a >> 8;
                atomicAdd((float*)(smc + ASM_S + r * S_STRIDE_B + dst * 4),
                          g_ew[eid * 8 + h]);
            }
        }
        __syncthreads();
        // ---- softmax + P -> bf16 hi/lo (swizzled) ----
        #pragma unroll
        for (int rr = 0; rr < 4; ++rr) {
            int r = wid * 4 + rr;
            const float* srow = (const float*)(smc + ASM_S + r * S_STRIDE_B);
            float vals[8];
            float mx = -1e30f;
            #pragma unroll
            for (int i = 0; i < 8; ++i) {
                vals[i] = srow[lane + 32 * i];
                mx = fmaxf(mx, vals[i]);
            }
            mx = warp_max(mx);
            float sum = 0.f;
            #pragma unroll
            for (int i = 0; i < 8; ++i) { vals[i] = __expf(vals[i] - mx); sum += vals[i]; }
            sum = warp_sum(sum);
            float inv = __frcp_rn(sum);
            #pragma unroll
            for (int i = 0; i < 8; ++i) {
                float p = vals[i] * inv;
                int t = lane + 32 * i;
                __nv_bfloat16 ph = __float2bfloat16(p);
                __nv_bfloat16 pl = __float2bfloat16(p - __bfloat162float(ph));
                int cb = t >> 3;
                uint32_t off = ASM_P + r * 1024 + ((cb ^ (r & 7)) << 4) + ((2 * t) & 15);
                *(__nv_bfloat16*)(smc + off)       = ph;
                *(__nv_bfloat16*)(smc + off + 512) = pl;
            }
        }
        __syncthreads();
        // ---- P @ V: split-K, warp wid owns ksteps [wid*2, wid*2+2) ----
        // V is token-major; B fragments via ldmatrix.trans (rows = tokens).
        {
            float acc[2][4][4];
            #pragma unroll
            for (int i = 0; i < 2; ++i)
                #pragma unroll
                for (int j = 0; j < 4; ++j)
                    #pragma unroll
                    for (int q = 0; q < 4; ++q) acc[i][j][q] = 0.f;
            #pragma unroll
            for (int kk = 0; kk < 2; ++kk) {
                int ks = wid * 2 + kk;
                uint32_t ph[2][4], pl[2][4], vh[2][4], vl[2][4];
                #pragma unroll
                for (int mt = 0; mt < 2; ++mt) {
                    int row = mt * 16 + a_r;
                    int cb = ks * 2 + a_cb0;
                    uint32_t off = ASM_P + row * 1024 + ((cb ^ (row & 7)) << 4);
                    ldsm_x4(sb + off, ph[mt]);
                    ldsm_x4(sb + off + 512, pl[mt]);
                }
                #pragma unroll
                for (int bt = 0; bt < 2; ++bt) {      // bt = d16 block
                    int tok = ks * 16 + t_r;
                    int cbh = bt * 2 + t_dc;
                    uint32_t off = ASM_V + tok * 128 + (((cbh)     ^ (tok & 7)) << 4);
                    uint32_t ofl = ASM_V + tok * 128 + (((cbh + 4) ^ (tok & 7)) << 4);
                    ldsm_x4_trans(sb + off, vh[bt]);
                    ldsm_x4_trans(sb + ofl, vl[bt]);
                }
                #pragma unroll
                for (int mt = 0; mt < 2; ++mt)
                    #pragma unroll
                    for (int nt = 0; nt < 4; ++nt) {
                        int bt = nt >> 1, hf = (nt & 1) * 2;
                        mma16816(acc[mt][nt], ph[mt], vh[bt][hf], vh[bt][hf + 1]);
                        mma16816(acc[mt][nt], ph[mt], vl[bt][hf], vl[bt][hf + 1]);
                        mma16816(acc[mt][nt], pl[mt], vh[bt][hf], vh[bt][hf + 1]);
                    }
            }
            #pragma unroll
            for (int mt = 0; mt < 2; ++mt)
                #pragma unroll
                for (int nt = 0; nt < 4; ++nt) {
                    int row = mt * 16 + gid;
                    int col = nt * 8 + tig * 2;
                    *(float2*)(smc + ASM_R + wid * 4096 + row * 128 + col * 4) =
                        make_float2(acc[mt][nt][0], acc[mt][nt][1]);
                    *(float2*)(smc + ASM_R + wid * 4096 + (row + 8) * 128 + col * 4) =
                        make_float2(acc[mt][nt][2], acc[mt][nt][3]);
                }
        }
        __syncthreads();
        // ---- reduce 8 partials + residual + write ----
        {
            int row = tid >> 3, colb = (tid & 7) * 4;
            float4 s4 = make_float4(0.f, 0.f, 0.f, 0.f);
            #pragma unroll
            for (int w = 0; w < 8; ++w) {
                float4 t4 = *(const float4*)(smc + ASM_R + w * 4096 + row * 128 + colb * 4);
                s4.x += t4.x; s4.y += t4.y; s4.z += t4.z; s4.w += t4.w;
            }
            int gr = g * 256 + m0 + row;
            int col = h * 32 + colb;
            float4 xin = *(const float4*)(x + (size_t)gr * 256 + col);
            s4.x += xin.x; s4.y += xin.y; s4.z += xin.z; s4.w += xin.w;
            *(float4*)(xout + (size_t)gr * 256 + col) = s4;
        }
        __syncthreads();
    }
}

// ---------------------------------------------------------------------------
// Launch
// ---------------------------------------------------------------------------
extern "C" void kernel_launch(void* const* d_in, const int* in_sizes, int n_in,
                              void* d_out, int out_size) {
    const float* x    = (const float*)d_in[0];
    const void*  ei   =                d_in[1];
    const float* ea   = (const float*)d_in[2];
    const float* ln1w = (const float*)d_in[4];
    const float* ln1b = (const float*)d_in[5];
    const float* Wq   = (const float*)d_in[6];
    const float* bq   = (const float*)d_in[7];
    const float* Wk   = (const float*)d_in[8];
    const float* bk   = (const float*)d_in[9];
    const float* Wv   = (const float*)d_in[10];
    const float* bv   = (const float*)d_in[11];
    const float* We   = (const float*)d_in[12];
    const float* be   = (const float*)d_in[13];
    const float* ln2w = (const float*)d_in[14];
    const float* ln2b = (const float*)d_in[15];
    const float* Wf1  = (const float*)d_in[16];
    const float* bf1  = (const float*)d_in[17];
    const float* Wf2  = (const float*)d_in[18];
    const float* bf2  = (const float*)d_in[19];
    float* out = (float*)d_out;

    float *p_xout;
    __nv_bfloat16 *p_xnh, *p_xnl, *p_hh, *p_hl;
    cudaGetSymbolAddress((void**)&p_xout, g_xout);
    cudaGetSymbolAddress((void**)&p_xnh,  g_xn_hi);
    cudaGetSymbolAddress((void**)&p_xnl,  g_xn_lo);
    cudaGetSymbolAddress((void**)&p_hh,   g_h_hi);
    cudaGetSymbolAddress((void**)&p_hl,   g_h_lo);

    cudaFuncSetAttribute(attn_kernel, cudaFuncAttributeMaxDynamicSharedMemorySize, ATTN_SMEM);
    cudaFuncSetAttribute(qkv_kernel,  cudaFuncAttributeMaxDynamicSharedMemorySize, GEMM_SMEM);
    cudaFuncSetAttribute(ff1_kernel,  cudaFuncAttributeMaxDynamicSharedMemorySize, GEMM_SMEM);
    cudaFuncSetAttribute(ff2_kernel,  cudaFuncAttributeMaxDynamicSharedMemorySize, GEMM_SMEM);

    // prep (2 launches) + weight prep (1)
    detect_zero_kernel<<<GN_ / 256, 256>>>(ei);
    scatter_ew_kernel<<<E_ / 256, 256>>>(ei, ea, We, be);
    wprep_all_kernel<<<704, dim3(32, 8)>>>(Wq, Wk, Wv, Wf1, Wf2);

    // LN1 + QKV (writes attention-layout q/k/v)
    ln_split_kernel<<<GN_ / 8, 256>>>(x, ln1w, ln1b, p_xnh, p_xnl);
    qkv_kernel<<<dim3(GN_ / 128, OUT_ / 128, 3), 512, GEMM_SMEM>>>(bq, bk, bv);

    // tensor-core attention (+ residual)
    attn_kernel<<<G_ * H_, 256, ATTN_SMEM>>>(x, p_xout);

    // LN2 + FFN
    ln_split_kernel<<<GN_ / 8, 256>>>(p_xout, ln2w, ln2b, p_hh, p_hl);
    ff1_kernel<<<dim3(GN_ / 128, FF_ / 128), 512, GEMM_SMEM>>>(bf1);
    ff2_kernel<<<dim3(GN_ / 128, OUT_ / 128), 512, GEMM_SMEM>>>(bf2, out);
}